// round 1
// baseline (speedup 1.0000x reference)
#include <cuda_runtime.h>

#define BB 64
#define EE 1024
#define NN_ 512
#define DD 64
#define HH 128
#define TT 5

// scratch (device globals — no runtime allocation)
__device__ float g_edges[BB * EE * DD];   // 16 MB: H @ ori
__device__ float g_ef[BB * EE * DD];      // 16 MB: mixture MLP output

// ---------------------------------------------------------------------------
// K1: edges[b] = H[b] @ ori[b]    (M=1024, N=64, K=512) per batch
// CTA: 128 rows x 64 cols, 256 threads (16x16), 8x4 outputs/thread
// ---------------------------------------------------------------------------
__global__ __launch_bounds__(256) void k1_edges(const float* __restrict__ H,
                                                const float* __restrict__ ori) {
    __shared__ float As[128][36];   // [m][k], pad row to 36 (144B, 16B-aligned)
    __shared__ float Bs[32][64];    // [k][n]

    const int b   = blockIdx.y;
    const int m0  = blockIdx.x * 128;
    const int tid = threadIdx.x;
    const int tx  = tid & 15;       // col group
    const int ty  = tid >> 4;       // row group

    const float* Hb   = H   + (size_t)b * EE * NN_;
    const float* orib = ori + (size_t)b * NN_ * DD;

    float acc[8][4];
#pragma unroll
    for (int i = 0; i < 8; i++)
#pragma unroll
        for (int j = 0; j < 4; j++) acc[i][j] = 0.f;

    for (int k0 = 0; k0 < NN_; k0 += 32) {
        // A tile: 128x32 floats = 1024 float4, 4 per thread
#pragma unroll
        for (int p = 0; p < 4; p++) {
            int f  = tid + p * 256;
            int r  = f >> 3;
            int kq = f & 7;
            float4 v = *(const float4*)(Hb + (size_t)(m0 + r) * NN_ + k0 + kq * 4);
            *(float4*)&As[r][kq * 4] = v;
        }
        // B tile: 32x64 floats = 512 float4, 2 per thread
#pragma unroll
        for (int p = 0; p < 2; p++) {
            int f  = tid + p * 256;
            int r  = f >> 4;
            int cq = f & 15;
            float4 v = *(const float4*)(orib + (size_t)(k0 + r) * DD + cq * 4);
            *(float4*)&Bs[r][cq * 4] = v;
        }
        __syncthreads();
#pragma unroll 8
        for (int k = 0; k < 32; k++) {
            float a[8];
#pragma unroll
            for (int i = 0; i < 8; i++) a[i] = As[ty * 8 + i][k];
            float4 bv = *(const float4*)&Bs[k][tx * 4];
#pragma unroll
            for (int i = 0; i < 8; i++) {
                acc[i][0] += a[i] * bv.x;
                acc[i][1] += a[i] * bv.y;
                acc[i][2] += a[i] * bv.z;
                acc[i][3] += a[i] * bv.w;
            }
        }
        __syncthreads();
    }

    float* outb = g_edges + (size_t)b * EE * DD;
#pragma unroll
    for (int i = 0; i < 8; i++) {
        float4 v = make_float4(acc[i][0], acc[i][1], acc[i][2], acc[i][3]);
        *(float4*)(outb + (size_t)(m0 + ty * 8 + i) * DD + tx * 4) = v;
    }
}

// ---------------------------------------------------------------------------
// K2: per-edge mixture MLP.
// For each row x (64): y = sum_t w_t * ( relu(x@W1_t + b1_t) @ W2_t + b2_t )
// CTA: 128 rows, 256 threads. Loop over the 5 edge types, weights staged in smem.
// ---------------------------------------------------------------------------
#define K2_XS   (128 * 64)          // 8192
#define K2_W1S  (64 * 128)          // 8192
#define K2_HLD  132                 // padded Hs row stride
#define K2_HS   (128 * K2_HLD)      // 16896
#define K2_W2S  (128 * 64)          // 8192
#define K2_WDS  (128 * TT)          // 640
#define K2_SMEM_FLOATS (K2_XS + K2_W1S + K2_HS + K2_W2S + K2_WDS + 128 + 64)
#define K2_SMEM_BYTES  (K2_SMEM_FLOATS * 4)   // 169216

__global__ __launch_bounds__(256) void k2_mlp(const float* __restrict__ ed,
                                              const float* __restrict__ W1,
                                              const float* __restrict__ b1,
                                              const float* __restrict__ W2,
                                              const float* __restrict__ b2) {
    extern __shared__ float sm[];
    float* Xs  = sm;                 // [128][64]
    float* W1s = Xs + K2_XS;         // [64][128]
    float* Hs  = W1s + K2_W1S;       // [128][132]
    float* W2s = Hs + K2_HS;         // [128][64]
    float* wds = W2s + K2_W2S;       // [128][5]
    float* b1s = wds + K2_WDS;       // [128]
    float* b2s = b1s + 128;          // [64]

    const int row0 = blockIdx.x * 128;
    const int tid  = threadIdx.x;
    const int tx   = tid & 15;
    const int ty   = tid >> 4;

    // stage X (edges rows) and per-row mixture weights
#pragma unroll
    for (int p = 0; p < 8; p++) {
        int f = tid + p * 256;
        *(float4*)&Xs[f * 4] = *(const float4*)(g_edges + (size_t)row0 * DD + f * 4);
    }
    for (int f = tid; f < K2_WDS; f += 256) wds[f] = ed[(size_t)row0 * TT + f];

    float Y[8][4];
#pragma unroll
    for (int i = 0; i < 8; i++)
#pragma unroll
        for (int j = 0; j < 4; j++) Y[i][j] = 0.f;

    for (int t = 0; t < TT; t++) {
        __syncthreads();   // Xs/wds ready (t=0); W1s/W2s safe to overwrite (t>0)
        // stage this type's weights
#pragma unroll
        for (int p = 0; p < 8; p++) {
            int f = tid + p * 256;
            *(float4*)&W1s[f * 4] = *(const float4*)(W1 + (size_t)t * DD * HH + f * 4);
            *(float4*)&W2s[f * 4] = *(const float4*)(W2 + (size_t)t * HH * DD + f * 4);
        }
        if (tid < 128)      b1s[tid]       = b1[t * HH + tid];
        else if (tid < 192) b2s[tid - 128] = b2[t * DD + (tid - 128)];
        __syncthreads();

        // Hs = relu(Xs @ W1s + b1): each thread 8 rows x 8 cols
        float h[8][8];
#pragma unroll
        for (int i = 0; i < 8; i++)
#pragma unroll
            for (int j = 0; j < 8; j++) h[i][j] = 0.f;
#pragma unroll 4
        for (int k = 0; k < 64; k++) {
            float a[8];
#pragma unroll
            for (int i = 0; i < 8; i++) a[i] = Xs[(ty * 8 + i) * 64 + k];
            float4 bv0 = *(const float4*)&W1s[k * 128 + tx * 8];
            float4 bv1 = *(const float4*)&W1s[k * 128 + tx * 8 + 4];
#pragma unroll
            for (int i = 0; i < 8; i++) {
                h[i][0] += a[i] * bv0.x; h[i][1] += a[i] * bv0.y;
                h[i][2] += a[i] * bv0.z; h[i][3] += a[i] * bv0.w;
                h[i][4] += a[i] * bv1.x; h[i][5] += a[i] * bv1.y;
                h[i][6] += a[i] * bv1.z; h[i][7] += a[i] * bv1.w;
            }
        }
        {
            float4 c0 = *(const float4*)&b1s[tx * 8];
            float4 c1 = *(const float4*)&b1s[tx * 8 + 4];
#pragma unroll
            for (int i = 0; i < 8; i++) {
                float4 v0, v1;
                v0.x = fmaxf(h[i][0] + c0.x, 0.f);
                v0.y = fmaxf(h[i][1] + c0.y, 0.f);
                v0.z = fmaxf(h[i][2] + c0.z, 0.f);
                v0.w = fmaxf(h[i][3] + c0.w, 0.f);
                v1.x = fmaxf(h[i][4] + c1.x, 0.f);
                v1.y = fmaxf(h[i][5] + c1.y, 0.f);
                v1.z = fmaxf(h[i][6] + c1.z, 0.f);
                v1.w = fmaxf(h[i][7] + c1.w, 0.f);
                *(float4*)&Hs[(ty * 8 + i) * K2_HLD + tx * 8]     = v0;
                *(float4*)&Hs[(ty * 8 + i) * K2_HLD + tx * 8 + 4] = v1;
            }
        }
        __syncthreads();

        // acc = Hs @ W2s ; Y += w_row * (acc + b2)
        float acc[8][4];
#pragma unroll
        for (int i = 0; i < 8; i++)
#pragma unroll
            for (int j = 0; j < 4; j++) acc[i][j] = 0.f;
#pragma unroll 4
        for (int k = 0; k < 128; k++) {
            float a[8];
#pragma unroll
            for (int i = 0; i < 8; i++) a[i] = Hs[(ty * 8 + i) * K2_HLD + k];
            float4 bv = *(const float4*)&W2s[k * 64 + tx * 4];
#pragma unroll
            for (int i = 0; i < 8; i++) {
                acc[i][0] += a[i] * bv.x;
                acc[i][1] += a[i] * bv.y;
                acc[i][2] += a[i] * bv.z;
                acc[i][3] += a[i] * bv.w;
            }
        }
        {
            float4 c = *(const float4*)&b2s[tx * 4];
#pragma unroll
            for (int i = 0; i < 8; i++) {
                float w = wds[(ty * 8 + i) * TT + t];
                Y[i][0] += w * (acc[i][0] + c.x);
                Y[i][1] += w * (acc[i][1] + c.y);
                Y[i][2] += w * (acc[i][2] + c.z);
                Y[i][3] += w * (acc[i][3] + c.w);
            }
        }
    }

#pragma unroll
    for (int i = 0; i < 8; i++) {
        float4 v = make_float4(Y[i][0], Y[i][1], Y[i][2], Y[i][3]);
        *(float4*)(g_ef + (size_t)(row0 + ty * 8 + i) * DD + tx * 4) = v;
    }
}

// ---------------------------------------------------------------------------
// K3: node_agg[b] = H[b]^T @ edge_feature[b]   (M=512(n), N=64(d), K=1024(e))
// + fused concat copy of ori into out[..., 64:128]
// ---------------------------------------------------------------------------
__global__ __launch_bounds__(256) void k3_out(const float* __restrict__ H,
                                              const float* __restrict__ ori,
                                              float* __restrict__ out) {
    __shared__ float As[32][128];   // [k(e)][m(n)] — H rows are contiguous in n
    __shared__ float Bs[32][64];    // [k(e)][d]

    const int b   = blockIdx.y;
    const int n0  = blockIdx.x * 128;
    const int tid = threadIdx.x;
    const int tx  = tid & 15;
    const int ty  = tid >> 4;

    const float* Hb  = H    + (size_t)b * EE * NN_;
    const float* efb = g_ef + (size_t)b * EE * DD;

    float acc[8][4];
#pragma unroll
    for (int i = 0; i < 8; i++)
#pragma unroll
        for (int j = 0; j < 4; j++) acc[i][j] = 0.f;

    for (int e0 = 0; e0 < EE; e0 += 32) {
        // A tile: H[b][e0+r][n0+c], 32x128 = 1024 float4, 4/thread
#pragma unroll
        for (int p = 0; p < 4; p++) {
            int f  = tid + p * 256;
            int r  = f >> 5;
            int cq = f & 31;
            *(float4*)&As[r][cq * 4] =
                *(const float4*)(Hb + (size_t)(e0 + r) * NN_ + n0 + cq * 4);
        }
        // B tile: ef[e0+r][d], 32x64
#pragma unroll
        for (int p = 0; p < 2; p++) {
            int f  = tid + p * 256;
            int r  = f >> 4;
            int cq = f & 15;
            *(float4*)&Bs[r][cq * 4] =
                *(const float4*)(efb + (size_t)(e0 + r) * DD + cq * 4);
        }
        __syncthreads();
#pragma unroll 8
        for (int k = 0; k < 32; k++) {
            float4 a0 = *(const float4*)&As[k][ty * 8];
            float4 a1 = *(const float4*)&As[k][ty * 8 + 4];
            float  a[8] = {a0.x, a0.y, a0.z, a0.w, a1.x, a1.y, a1.z, a1.w};
            float4 bv = *(const float4*)&Bs[k][tx * 4];
#pragma unroll
            for (int i = 0; i < 8; i++) {
                acc[i][0] += a[i] * bv.x;
                acc[i][1] += a[i] * bv.y;
                acc[i][2] += a[i] * bv.z;
                acc[i][3] += a[i] * bv.w;
            }
        }
        __syncthreads();
    }

    float*       outb = out + (size_t)b * NN_ * (2 * DD);
    const float* orib = ori + (size_t)b * NN_ * DD;
#pragma unroll
    for (int i = 0; i < 8; i++) {
        int n = n0 + ty * 8 + i;
        float4 v = make_float4(acc[i][0], acc[i][1], acc[i][2], acc[i][3]);
        *(float4*)(outb + (size_t)n * (2 * DD) + tx * 4) = v;
    }
    // concat half: copy ori rows (128 x 64 = 2048 float4, 8/thread)
#pragma unroll
    for (int p = 0; p < 8; p++) {
        int f  = tid + p * 256;
        int r  = f >> 4;
        int cq = f & 15;
        float4 v = *(const float4*)(orib + (size_t)(n0 + r) * DD + cq * 4);
        *(float4*)(outb + (size_t)(n0 + r) * (2 * DD) + DD + cq * 4) = v;
    }
}

// ---------------------------------------------------------------------------
extern "C" void kernel_launch(void* const* d_in, const int* in_sizes, int n_in,
                              void* d_out, int out_size) {
    const float* ed  = (const float*)d_in[0];  // [B,E,T]
    const float* H   = (const float*)d_in[1];  // [B,E,N]
    const float* ori = (const float*)d_in[2];  // [B,N,D]
    const float* W1  = (const float*)d_in[3];  // [T,D,HID]
    const float* b1  = (const float*)d_in[4];  // [T,HID]
    const float* W2  = (const float*)d_in[5];  // [T,HID,D]
    const float* b2  = (const float*)d_in[6];  // [T,D]
    float* out = (float*)d_out;                // [B,N,2D]

    // opt-in to >48KB dynamic smem for the MLP kernel (idempotent, capture-safe)
    cudaFuncSetAttribute(k2_mlp, cudaFuncAttributeMaxDynamicSharedMemorySize,
                         K2_SMEM_BYTES);

    dim3 g1(EE / 128, BB);
    k1_edges<<<g1, 256>>>(H, ori);

    k2_mlp<<<(BB * EE) / 128, 256, K2_SMEM_BYTES>>>(ed, W1, b1, W2, b2);

    dim3 g3(NN_ / 128, BB);
    k3_out<<<g3, 256>>>(H, ori, out);
}

// round 2
// speedup vs baseline: 1.9855x; 1.9855x over previous
#include <cuda_runtime.h>
#include <cstdint>

#define BB 64
#define EE 1024
#define NN_ 512
#define DD 64
#define HH 128
#define TT 5

// scratch (device globals — no runtime allocation)
__device__ float g_edges[BB * EE * DD];   // 16 MB: H @ ori
__device__ float g_ef[BB * EE * DD];      // 16 MB: mixture MLP output

// ---------------------------------------------------------------------------
// helpers: tf32 convert + m16n8k8 tf32 MMA
// ---------------------------------------------------------------------------
__device__ __forceinline__ float4 cvt4_tf32(float4 v) {
    uint32_t x, y, z, w;
    asm("cvt.rna.tf32.f32 %0, %1;" : "=r"(x) : "f"(v.x));
    asm("cvt.rna.tf32.f32 %0, %1;" : "=r"(y) : "f"(v.y));
    asm("cvt.rna.tf32.f32 %0, %1;" : "=r"(z) : "f"(v.z));
    asm("cvt.rna.tf32.f32 %0, %1;" : "=r"(w) : "f"(v.w));
    float4 r;
    r.x = __uint_as_float(x); r.y = __uint_as_float(y);
    r.z = __uint_as_float(z); r.w = __uint_as_float(w);
    return r;
}
__device__ __forceinline__ uint32_t cvt_tf32(float v) {
    uint32_t x;
    asm("cvt.rna.tf32.f32 %0, %1;" : "=r"(x) : "f"(v));
    return x;
}
__device__ __forceinline__ void mma_tf32(float c[4], const uint32_t a[4],
                                         const uint32_t b[2]) {
    asm volatile(
        "mma.sync.aligned.m16n8k8.row.col.f32.tf32.tf32.f32 "
        "{%0,%1,%2,%3}, {%4,%5,%6,%7}, {%8,%9}, {%0,%1,%2,%3};"
        : "+f"(c[0]), "+f"(c[1]), "+f"(c[2]), "+f"(c[3])
        : "r"(a[0]), "r"(a[1]), "r"(a[2]), "r"(a[3]), "r"(b[0]), "r"(b[1]));
}
#define BITS(x) __float_as_uint(x)

// ---------------------------------------------------------------------------
// K1: edges[b] = H[b] @ ori[b]   (M=1024, N=64, K=512) per batch, tf32 MMA
// CTA 128x64, 8 warps (4m x 2n), warp tile 32x32
// ---------------------------------------------------------------------------
__global__ __launch_bounds__(256) void k1_edges(const float* __restrict__ H,
                                                const float* __restrict__ ori) {
    __shared__ float As[128 * 36];  // [m][k] stride 36 (conflict-free frags)
    __shared__ float Bs[32 * 68];   // [k][n] stride 68

    const int b   = blockIdx.y;
    const int m0  = blockIdx.x * 128;
    const int tid = threadIdx.x;
    const int wid = tid >> 5, lane = tid & 31;
    const int g = lane >> 2, t = lane & 3;
    const int wm = (wid >> 1) * 32, wn = (wid & 1) * 32;

    const float* Hb   = H   + (size_t)b * EE * NN_;
    const float* orib = ori + (size_t)b * NN_ * DD;

    float acc[2][4][4];
#pragma unroll
    for (int mi = 0; mi < 2; mi++)
#pragma unroll
        for (int ni = 0; ni < 4; ni++)
#pragma unroll
            for (int j = 0; j < 4; j++) acc[mi][ni][j] = 0.f;

    for (int k0 = 0; k0 < NN_; k0 += 32) {
#pragma unroll
        for (int p = 0; p < 4; p++) {   // A: 128x32 -> 1024 float4
            int f = tid + p * 256;
            int r = f >> 3, kq = f & 7;
            float4 v = *(const float4*)(Hb + (size_t)(m0 + r) * NN_ + k0 + kq * 4);
            *(float4*)&As[r * 36 + kq * 4] = cvt4_tf32(v);
        }
#pragma unroll
        for (int p = 0; p < 2; p++) {   // B: 32x64 -> 512 float4
            int f = tid + p * 256;
            int r = f >> 4, cq = f & 15;
            float4 v = *(const float4*)(orib + (size_t)(k0 + r) * DD + cq * 4);
            *(float4*)&Bs[r * 68 + cq * 4] = cvt4_tf32(v);
        }
        __syncthreads();
#pragma unroll
        for (int kk = 0; kk < 4; kk++) {
            uint32_t a[2][4], bf[4][2];
#pragma unroll
            for (int mi = 0; mi < 2; mi++) {
                int mr = wm + 16 * mi;
                a[mi][0] = BITS(As[(mr + g) * 36 + kk * 8 + t]);
                a[mi][1] = BITS(As[(mr + 8 + g) * 36 + kk * 8 + t]);
                a[mi][2] = BITS(As[(mr + g) * 36 + kk * 8 + t + 4]);
                a[mi][3] = BITS(As[(mr + 8 + g) * 36 + kk * 8 + t + 4]);
            }
#pragma unroll
            for (int ni = 0; ni < 4; ni++) {
                bf[ni][0] = BITS(Bs[(kk * 8 + t) * 68 + wn + 8 * ni + g]);
                bf[ni][1] = BITS(Bs[(kk * 8 + t + 4) * 68 + wn + 8 * ni + g]);
            }
#pragma unroll
            for (int mi = 0; mi < 2; mi++)
#pragma unroll
                for (int ni = 0; ni < 4; ni++) mma_tf32(acc[mi][ni], a[mi], bf[ni]);
        }
        __syncthreads();
    }

    float* outb = g_edges + (size_t)b * EE * DD;
#pragma unroll
    for (int mi = 0; mi < 2; mi++)
#pragma unroll
        for (int ni = 0; ni < 4; ni++) {
            int r1 = m0 + wm + 16 * mi + g, r2 = r1 + 8;
            int c  = wn + 8 * ni + 2 * t;
            *(float2*)(outb + (size_t)r1 * DD + c) =
                make_float2(acc[mi][ni][0], acc[mi][ni][1]);
            *(float2*)(outb + (size_t)r2 * DD + c) =
                make_float2(acc[mi][ni][2], acc[mi][ni][3]);
        }
}

// ---------------------------------------------------------------------------
// K2: per-edge mixture MLP (tf32 MMA for both layers)
// CTA: 128 rows; GEMM1 warp tile 32x64, GEMM2 warp tile 32x32
// ---------------------------------------------------------------------------
#define K2_XS   (128 * 68)
#define K2_W1S  (64 * 132)
#define K2_HS   (128 * 132)
#define K2_W2S  (128 * 68)
#define K2_WDS  (128 * TT)
#define K2_SMEM_FLOATS (K2_XS + K2_W1S + K2_HS + K2_W2S + K2_WDS + 128 + 64)
#define K2_SMEM_BYTES  (K2_SMEM_FLOATS * 4)

__global__ __launch_bounds__(256) void k2_mlp(const float* __restrict__ ed,
                                              const float* __restrict__ W1,
                                              const float* __restrict__ b1,
                                              const float* __restrict__ W2,
                                              const float* __restrict__ b2) {
    extern __shared__ float sm[];
    float* Xs  = sm;                 // [128][68] tf32
    float* W1s = Xs + K2_XS;         // [64][132] tf32
    float* Hs  = W1s + K2_W1S;       // [128][132] tf32
    float* W2s = Hs + K2_HS;         // [128][68] tf32
    float* wds = W2s + K2_W2S;       // [128][5]  fp32
    float* b1s = wds + K2_WDS;       // [128]
    float* b2s = b1s + 128;          // [64]

    const int row0 = blockIdx.x * 128;
    const int tid  = threadIdx.x;
    const int wid  = tid >> 5, lane = tid & 31;
    const int g = lane >> 2, t = lane & 3;
    const int wm = (wid >> 1) * 32;           // shared by both GEMMs
    const int wn1 = (wid & 1) * 64;           // GEMM1 n-offset
    const int wn2 = (wid & 1) * 32;           // GEMM2 n-offset

    // stage X (tf32) and mixture weights
#pragma unroll
    for (int p = 0; p < 8; p++) {
        int f = tid + p * 256;
        int r = f >> 4, cq = f & 15;
        float4 v = *(const float4*)(g_edges + (size_t)(row0 + r) * DD + cq * 4);
        *(float4*)&Xs[r * 68 + cq * 4] = cvt4_tf32(v);
    }
    for (int f = tid; f < K2_WDS; f += 256) wds[f] = ed[(size_t)row0 * TT + f];

    float Y[2][4][4];
#pragma unroll
    for (int mi = 0; mi < 2; mi++)
#pragma unroll
        for (int ni = 0; ni < 4; ni++)
#pragma unroll
            for (int j = 0; j < 4; j++) Y[mi][ni][j] = 0.f;

    for (int et = 0; et < TT; et++) {
        __syncthreads();   // Xs/wds ready (et=0); W1s/W2s/Hs safe to overwrite
#pragma unroll
        for (int p = 0; p < 8; p++) {
            int f = tid + p * 256;
            {   // W1: [64][128]
                int r = f >> 5, cq = f & 31;
                float4 v = *(const float4*)(W1 + (size_t)et * DD * HH + r * HH + cq * 4);
                *(float4*)&W1s[r * 132 + cq * 4] = cvt4_tf32(v);
            }
            {   // W2: [128][64]
                int r = f >> 4, cq = f & 15;
                float4 v = *(const float4*)(W2 + (size_t)et * HH * DD + r * DD + cq * 4);
                *(float4*)&W2s[r * 68 + cq * 4] = cvt4_tf32(v);
            }
        }
        if (tid < 128)      b1s[tid]       = b1[et * HH + tid];
        else if (tid < 192) b2s[tid - 128] = b2[et * DD + (tid - 128)];
        __syncthreads();

        // GEMM1: h = relu(X @ W1 + b1)  (128x128, k=64)
        float hacc[2][8][4];
#pragma unroll
        for (int mi = 0; mi < 2; mi++)
#pragma unroll
            for (int ni = 0; ni < 8; ni++)
#pragma unroll
                for (int j = 0; j < 4; j++) hacc[mi][ni][j] = 0.f;
#pragma unroll
        for (int kk = 0; kk < 8; kk++) {
            uint32_t a[2][4], bf[8][2];
#pragma unroll
            for (int mi = 0; mi < 2; mi++) {
                int mr = wm + 16 * mi;
                a[mi][0] = BITS(Xs[(mr + g) * 68 + kk * 8 + t]);
                a[mi][1] = BITS(Xs[(mr + 8 + g) * 68 + kk * 8 + t]);
                a[mi][2] = BITS(Xs[(mr + g) * 68 + kk * 8 + t + 4]);
                a[mi][3] = BITS(Xs[(mr + 8 + g) * 68 + kk * 8 + t + 4]);
            }
#pragma unroll
            for (int ni = 0; ni < 8; ni++) {
                bf[ni][0] = BITS(W1s[(kk * 8 + t) * 132 + wn1 + 8 * ni + g]);
                bf[ni][1] = BITS(W1s[(kk * 8 + t + 4) * 132 + wn1 + 8 * ni + g]);
            }
#pragma unroll
            for (int mi = 0; mi < 2; mi++)
#pragma unroll
                for (int ni = 0; ni < 8; ni++) mma_tf32(hacc[mi][ni], a[mi], bf[ni]);
        }
        // bias + relu + tf32 + store Hs
#pragma unroll
        for (int mi = 0; mi < 2; mi++) {
            int r1 = wm + 16 * mi + g, r2 = r1 + 8;
#pragma unroll
            for (int ni = 0; ni < 8; ni++) {
                int c = wn1 + 8 * ni + 2 * t;
                float bx = b1s[c], by = b1s[c + 1];
                float h0 = fmaxf(hacc[mi][ni][0] + bx, 0.f);
                float h1 = fmaxf(hacc[mi][ni][1] + by, 0.f);
                float h2 = fmaxf(hacc[mi][ni][2] + bx, 0.f);
                float h3 = fmaxf(hacc[mi][ni][3] + by, 0.f);
                *(float2*)&Hs[r1 * 132 + c] = make_float2(
                    __uint_as_float(cvt_tf32(h0)), __uint_as_float(cvt_tf32(h1)));
                *(float2*)&Hs[r2 * 132 + c] = make_float2(
                    __uint_as_float(cvt_tf32(h2)), __uint_as_float(cvt_tf32(h3)));
            }
        }
        __syncthreads();

        // GEMM2: acc2 = h @ W2  (128x64, k=128); Y += w_row * (acc2 + b2)
        float acc2[2][4][4];
#pragma unroll
        for (int mi = 0; mi < 2; mi++)
#pragma unroll
            for (int ni = 0; ni < 4; ni++)
#pragma unroll
                for (int j = 0; j < 4; j++) acc2[mi][ni][j] = 0.f;
#pragma unroll
        for (int kk = 0; kk < 16; kk++) {
            uint32_t a[2][4], bf[4][2];
#pragma unroll
            for (int mi = 0; mi < 2; mi++) {
                int mr = wm + 16 * mi;
                a[mi][0] = BITS(Hs[(mr + g) * 132 + kk * 8 + t]);
                a[mi][1] = BITS(Hs[(mr + 8 + g) * 132 + kk * 8 + t]);
                a[mi][2] = BITS(Hs[(mr + g) * 132 + kk * 8 + t + 4]);
                a[mi][3] = BITS(Hs[(mr + 8 + g) * 132 + kk * 8 + t + 4]);
            }
#pragma unroll
            for (int ni = 0; ni < 4; ni++) {
                bf[ni][0] = BITS(W2s[(kk * 8 + t) * 68 + wn2 + 8 * ni + g]);
                bf[ni][1] = BITS(W2s[(kk * 8 + t + 4) * 68 + wn2 + 8 * ni + g]);
            }
#pragma unroll
            for (int mi = 0; mi < 2; mi++)
#pragma unroll
                for (int ni = 0; ni < 4; ni++) mma_tf32(acc2[mi][ni], a[mi], bf[ni]);
        }
#pragma unroll
        for (int mi = 0; mi < 2; mi++) {
            int r1 = wm + 16 * mi + g, r2 = r1 + 8;
            float wA = wds[r1 * TT + et];
            float wB = wds[r2 * TT + et];
#pragma unroll
            for (int ni = 0; ni < 4; ni++) {
                int c = wn2 + 8 * ni + 2 * t;
                float bx = b2s[c], by = b2s[c + 1];
                Y[mi][ni][0] += wA * (acc2[mi][ni][0] + bx);
                Y[mi][ni][1] += wA * (acc2[mi][ni][1] + by);
                Y[mi][ni][2] += wB * (acc2[mi][ni][2] + bx);
                Y[mi][ni][3] += wB * (acc2[mi][ni][3] + by);
            }
        }
    }

#pragma unroll
    for (int mi = 0; mi < 2; mi++)
#pragma unroll
        for (int ni = 0; ni < 4; ni++) {
            int r1 = row0 + wm + 16 * mi + g, r2 = r1 + 8;
            int c  = wn2 + 8 * ni + 2 * t;
            *(float2*)(g_ef + (size_t)r1 * DD + c) =
                make_float2(Y[mi][ni][0], Y[mi][ni][1]);
            *(float2*)(g_ef + (size_t)r2 * DD + c) =
                make_float2(Y[mi][ni][2], Y[mi][ni][3]);
        }
}

// ---------------------------------------------------------------------------
// K3: node_agg[b] = H[b]^T @ ef[b]  (M=512(n), N=64(d), K=1024(e)) + concat ori
// CTA 128x64, warp tile 32x32; A read transposed from Hs[k][m]
// ---------------------------------------------------------------------------
__global__ __launch_bounds__(256) void k3_out(const float* __restrict__ H,
                                              const float* __restrict__ ori,
                                              float* __restrict__ out) {
    __shared__ float Hs[32 * 132];  // [k(e)][m(n)] stride 132
    __shared__ float Bs[32 * 68];   // [k(e)][d]   stride 68

    const int b   = blockIdx.y;
    const int n0  = blockIdx.x * 128;
    const int tid = threadIdx.x;
    const int wid = tid >> 5, lane = tid & 31;
    const int g = lane >> 2, t = lane & 3;
    const int wm = (wid >> 1) * 32, wn = (wid & 1) * 32;

    const float* Hb  = H    + (size_t)b * EE * NN_;
    const float* efb = g_ef + (size_t)b * EE * DD;

    float acc[2][4][4];
#pragma unroll
    for (int mi = 0; mi < 2; mi++)
#pragma unroll
        for (int ni = 0; ni < 4; ni++)
#pragma unroll
            for (int j = 0; j < 4; j++) acc[mi][ni][j] = 0.f;

    for (int e0 = 0; e0 < EE; e0 += 32) {
#pragma unroll
        for (int p = 0; p < 4; p++) {   // Hs: 32x128
            int f = tid + p * 256;
            int r = f >> 5, cq = f & 31;
            float4 v = *(const float4*)(Hb + (size_t)(e0 + r) * NN_ + n0 + cq * 4);
            *(float4*)&Hs[r * 132 + cq * 4] = cvt4_tf32(v);
        }
#pragma unroll
        for (int p = 0; p < 2; p++) {   // Bs: 32x64
            int f = tid + p * 256;
            int r = f >> 4, cq = f & 15;
            float4 v = *(const float4*)(efb + (size_t)(e0 + r) * DD + cq * 4);
            *(float4*)&Bs[r * 68 + cq * 4] = cvt4_tf32(v);
        }
        __syncthreads();
#pragma unroll
        for (int kk = 0; kk < 4; kk++) {
            uint32_t a[2][4], bf[4][2];
#pragma unroll
            for (int mi = 0; mi < 2; mi++) {
                int mr = wm + 16 * mi;   // A[m][k] = Hs[k][m]
                a[mi][0] = BITS(Hs[(kk * 8 + t) * 132 + mr + g]);
                a[mi][1] = BITS(Hs[(kk * 8 + t) * 132 + mr + 8 + g]);
                a[mi][2] = BITS(Hs[(kk * 8 + t + 4) * 132 + mr + g]);
                a[mi][3] = BITS(Hs[(kk * 8 + t + 4) * 132 + mr + 8 + g]);
            }
#pragma unroll
            for (int ni = 0; ni < 4; ni++) {
                bf[ni][0] = BITS(Bs[(kk * 8 + t) * 68 + wn + 8 * ni + g]);
                bf[ni][1] = BITS(Bs[(kk * 8 + t + 4) * 68 + wn + 8 * ni + g]);
            }
#pragma unroll
            for (int mi = 0; mi < 2; mi++)
#pragma unroll
                for (int ni = 0; ni < 4; ni++) mma_tf32(acc[mi][ni], a[mi], bf[ni]);
        }
        __syncthreads();
    }

    float*       outb = out + (size_t)b * NN_ * (2 * DD);
    const float* orib = ori + (size_t)b * NN_ * DD;
#pragma unroll
    for (int mi = 0; mi < 2; mi++)
#pragma unroll
        for (int ni = 0; ni < 4; ni++) {
            int r1 = n0 + wm + 16 * mi + g, r2 = r1 + 8;
            int c  = wn + 8 * ni + 2 * t;
            *(float2*)(outb + (size_t)r1 * (2 * DD) + c) =
                make_float2(acc[mi][ni][0], acc[mi][ni][1]);
            *(float2*)(outb + (size_t)r2 * (2 * DD) + c) =
                make_float2(acc[mi][ni][2], acc[mi][ni][3]);
        }
    // concat half: copy ori rows (128 x 64 = 2048 float4, 8/thread)
#pragma unroll
    for (int p = 0; p < 8; p++) {
        int f = tid + p * 256;
        int r = f >> 4, cq = f & 15;
        float4 v = *(const float4*)(orib + (size_t)(n0 + r) * DD + cq * 4);
        *(float4*)(outb + (size_t)(n0 + r) * (2 * DD) + DD + cq * 4) = v;
    }
}

// ---------------------------------------------------------------------------
extern "C" void kernel_launch(void* const* d_in, const int* in_sizes, int n_in,
                              void* d_out, int out_size) {
    const float* ed  = (const float*)d_in[0];  // [B,E,T]
    const float* H   = (const float*)d_in[1];  // [B,E,N]
    const float* ori = (const float*)d_in[2];  // [B,N,D]
    const float* W1  = (const float*)d_in[3];  // [T,D,HID]
    const float* b1  = (const float*)d_in[4];  // [T,HID]
    const float* W2  = (const float*)d_in[5];  // [T,HID,D]
    const float* b2  = (const float*)d_in[6];  // [T,D]
    float* out = (float*)d_out;                // [B,N,2D]

    cudaFuncSetAttribute(k2_mlp, cudaFuncAttributeMaxDynamicSharedMemorySize,
                         K2_SMEM_BYTES);

    dim3 g1(EE / 128, BB);
    k1_edges<<<g1, 256>>>(H, ori);

    k2_mlp<<<(BB * EE) / 128, 256, K2_SMEM_BYTES>>>(ed, W1, b1, W2, b2);

    dim3 g3(NN_ / 128, BB);
    k3_out<<<g3, 256>>>(H, ori, out);
}

// round 3
// speedup vs baseline: 2.6655x; 1.3425x over previous
#include <cuda_runtime.h>
#include <cstdint>

#define BB 64
#define EE 1024
#define NN_ 512
#define DD 64
#define HH 128
#define TT 5

// scratch (device globals — no runtime allocation)
__device__ float g_edges[BB * EE * DD];   // 16 MB: H @ ori
__device__ float g_ef[BB * EE * DD];      // 16 MB: mixture MLP output

// ---------------------------------------------------------------------------
// helpers
// ---------------------------------------------------------------------------
__device__ __forceinline__ float4 cvt4_tf32(float4 v) {
    uint32_t x, y, z, w;
    asm("cvt.rna.tf32.f32 %0, %1;" : "=r"(x) : "f"(v.x));
    asm("cvt.rna.tf32.f32 %0, %1;" : "=r"(y) : "f"(v.y));
    asm("cvt.rna.tf32.f32 %0, %1;" : "=r"(z) : "f"(v.z));
    asm("cvt.rna.tf32.f32 %0, %1;" : "=r"(w) : "f"(v.w));
    float4 r;
    r.x = __uint_as_float(x); r.y = __uint_as_float(y);
    r.z = __uint_as_float(z); r.w = __uint_as_float(w);
    return r;
}
__device__ __forceinline__ uint32_t cvt_tf32(float v) {
    uint32_t x;
    asm("cvt.rna.tf32.f32 %0, %1;" : "=r"(x) : "f"(v));
    return x;
}
__device__ __forceinline__ void mma_tf32(float c[4], const uint32_t a[4],
                                         const uint32_t b[2]) {
    asm volatile(
        "mma.sync.aligned.m16n8k8.row.col.f32.tf32.tf32.f32 "
        "{%0,%1,%2,%3}, {%4,%5,%6,%7}, {%8,%9}, {%0,%1,%2,%3};"
        : "+f"(c[0]), "+f"(c[1]), "+f"(c[2]), "+f"(c[3])
        : "r"(a[0]), "r"(a[1]), "r"(a[2]), "r"(a[3]), "r"(b[0]), "r"(b[1]));
}
#define BITS(x) __float_as_uint(x)

// ---------------------------------------------------------------------------
// K1: edges[b] = H[b] @ ori[b]  (M=1024, N=64, K=512), double-buffered smem
// CTA 128x64, 8 warps (4m x 2n), warp tile 32x32
// As stride 36 (A-frags: rows by g -> 4g+t banks), Bs stride 72 (rows by t -> 8t+g)
// ---------------------------------------------------------------------------
#define K1_ASZ (128 * 36)
#define K1_BSZ (32 * 72)
#define K1_BUF (K1_ASZ + K1_BSZ)
#define K1_SMEM_BYTES (2 * K1_BUF * 4)

__global__ __launch_bounds__(256) void k1_edges(const float* __restrict__ H,
                                                const float* __restrict__ ori) {
    extern __shared__ float sm1[];

    const int b   = blockIdx.y;
    const int m0  = blockIdx.x * 128;
    const int tid = threadIdx.x;
    const int wid = tid >> 5, lane = tid & 31;
    const int g = lane >> 2, t = lane & 3;
    const int wm = (wid >> 1) * 32, wn = (wid & 1) * 32;

    const float* Hb   = H   + (size_t)b * EE * NN_;
    const float* orib = ori + (size_t)b * NN_ * DD;

    float acc[2][4][4];
#pragma unroll
    for (int mi = 0; mi < 2; mi++)
#pragma unroll
        for (int ni = 0; ni < 4; ni++)
#pragma unroll
            for (int j = 0; j < 4; j++) acc[mi][ni][j] = 0.f;

    float4 ra[4], rb[2];
    // prologue loads (k0 = 0)
#pragma unroll
    for (int p = 0; p < 4; p++) {
        int f = tid + p * 256;
        ra[p] = *(const float4*)(Hb + (size_t)(m0 + (f >> 3)) * NN_ + (f & 7) * 4);
    }
#pragma unroll
    for (int p = 0; p < 2; p++) {
        int f = tid + p * 256;
        rb[p] = *(const float4*)(orib + (size_t)(f >> 4) * DD + (f & 15) * 4);
    }
    {
        float* A0 = sm1; float* B0 = sm1 + K1_ASZ;
#pragma unroll
        for (int p = 0; p < 4; p++) {
            int f = tid + p * 256;
            *(float4*)&A0[(f >> 3) * 36 + (f & 7) * 4] = cvt4_tf32(ra[p]);
        }
#pragma unroll
        for (int p = 0; p < 2; p++) {
            int f = tid + p * 256;
            *(float4*)&B0[(f >> 4) * 72 + (f & 15) * 4] = cvt4_tf32(rb[p]);
        }
    }
    __syncthreads();

    int buf = 0;
    for (int k0 = 0; k0 < NN_; k0 += 32) {
        const int kn = k0 + 32;
        if (kn < NN_) {
#pragma unroll
            for (int p = 0; p < 4; p++) {
                int f = tid + p * 256;
                ra[p] = *(const float4*)(Hb + (size_t)(m0 + (f >> 3)) * NN_ + kn + (f & 7) * 4);
            }
#pragma unroll
            for (int p = 0; p < 2; p++) {
                int f = tid + p * 256;
                rb[p] = *(const float4*)(orib + (size_t)(kn + (f >> 4)) * DD + (f & 15) * 4);
            }
        }
        const float* A_ = sm1 + buf * K1_BUF;
        const float* B_ = A_ + K1_ASZ;
#pragma unroll
        for (int kk = 0; kk < 4; kk++) {
            uint32_t a[2][4], bf[4][2];
#pragma unroll
            for (int mi = 0; mi < 2; mi++) {
                int mr = wm + 16 * mi;
                a[mi][0] = BITS(A_[(mr + g) * 36 + kk * 8 + t]);
                a[mi][1] = BITS(A_[(mr + 8 + g) * 36 + kk * 8 + t]);
                a[mi][2] = BITS(A_[(mr + g) * 36 + kk * 8 + t + 4]);
                a[mi][3] = BITS(A_[(mr + 8 + g) * 36 + kk * 8 + t + 4]);
            }
#pragma unroll
            for (int ni = 0; ni < 4; ni++) {
                bf[ni][0] = BITS(B_[(kk * 8 + t) * 72 + wn + 8 * ni + g]);
                bf[ni][1] = BITS(B_[(kk * 8 + t + 4) * 72 + wn + 8 * ni + g]);
            }
#pragma unroll
            for (int mi = 0; mi < 2; mi++)
#pragma unroll
                for (int ni = 0; ni < 4; ni++) mma_tf32(acc[mi][ni], a[mi], bf[ni]);
        }
        if (kn < NN_) {
            float* An = sm1 + (buf ^ 1) * K1_BUF;
            float* Bn = An + K1_ASZ;
#pragma unroll
            for (int p = 0; p < 4; p++) {
                int f = tid + p * 256;
                *(float4*)&An[(f >> 3) * 36 + (f & 7) * 4] = cvt4_tf32(ra[p]);
            }
#pragma unroll
            for (int p = 0; p < 2; p++) {
                int f = tid + p * 256;
                *(float4*)&Bn[(f >> 4) * 72 + (f & 15) * 4] = cvt4_tf32(rb[p]);
            }
        }
        __syncthreads();
        buf ^= 1;
    }

    float* outb = g_edges + (size_t)b * EE * DD;
#pragma unroll
    for (int mi = 0; mi < 2; mi++)
#pragma unroll
        for (int ni = 0; ni < 4; ni++) {
            int r1 = m0 + wm + 16 * mi + g, r2 = r1 + 8;
            int c  = wn + 8 * ni + 2 * t;
            *(float2*)(outb + (size_t)r1 * DD + c) =
                make_float2(acc[mi][ni][0], acc[mi][ni][1]);
            *(float2*)(outb + (size_t)r2 * DD + c) =
                make_float2(acc[mi][ni][2], acc[mi][ni][3]);
        }
}

// ---------------------------------------------------------------------------
// K2: per-edge mixture MLP, weight prefetch across the type loop
// Xs stride 68 (A), W1s stride 136 (B), Hs stride 132 (A), W2s stride 72 (B)
// ---------------------------------------------------------------------------
#define K2_XS   (128 * 68)
#define K2_W1S  (64 * 136)
#define K2_HS   (128 * 132)
#define K2_W2S  (128 * 72)
#define K2_WDS  (128 * TT)
#define K2_SMEM_FLOATS (K2_XS + K2_W1S + K2_HS + K2_W2S + K2_WDS + 2*128 + 2*64)
#define K2_SMEM_BYTES  (K2_SMEM_FLOATS * 4)

__global__ __launch_bounds__(256) void k2_mlp(const float* __restrict__ ed,
                                              const float* __restrict__ W1,
                                              const float* __restrict__ b1,
                                              const float* __restrict__ W2,
                                              const float* __restrict__ b2) {
    extern __shared__ float sm[];
    float* Xs  = sm;
    float* W1s = Xs + K2_XS;
    float* Hs  = W1s + K2_W1S;
    float* W2s = Hs + K2_HS;
    float* wds = W2s + K2_W2S;
    float* b1s = wds + K2_WDS;      // [2][128]
    float* b2s = b1s + 256;         // [2][64]

    const int row0 = blockIdx.x * 128;
    const int tid  = threadIdx.x;
    const int wid  = tid >> 5, lane = tid & 31;
    const int g = lane >> 2, t = lane & 3;
    const int wm  = (wid >> 1) * 32;
    const int wn1 = (wid & 1) * 64;
    const int wn2 = (wid & 1) * 32;

    // stage X (tf32), mixture weights, type-0 weights/biases
#pragma unroll
    for (int p = 0; p < 8; p++) {
        int f = tid + p * 256;
        float4 v = *(const float4*)(g_edges + (size_t)(row0 + (f >> 4)) * DD + (f & 15) * 4);
        *(float4*)&Xs[(f >> 4) * 68 + (f & 15) * 4] = cvt4_tf32(v);
    }
    for (int f = tid; f < K2_WDS; f += 256) wds[f] = ed[(size_t)row0 * TT + f];
#pragma unroll
    for (int p = 0; p < 8; p++) {
        int f = tid + p * 256;
        float4 v1 = *(const float4*)(W1 + (size_t)f * 4);
        *(float4*)&W1s[(f >> 5) * 136 + (f & 31) * 4] = cvt4_tf32(v1);
        float4 v2 = *(const float4*)(W2 + (size_t)f * 4);
        *(float4*)&W2s[(f >> 4) * 72 + (f & 15) * 4] = cvt4_tf32(v2);
    }
    if (tid < 128)      b1s[tid]       = b1[tid];
    else if (tid < 192) b2s[tid - 128] = b2[tid - 128];

    float Y[2][4][4];
#pragma unroll
    for (int mi = 0; mi < 2; mi++)
#pragma unroll
        for (int ni = 0; ni < 4; ni++)
#pragma unroll
            for (int j = 0; j < 4; j++) Y[mi][ni][j] = 0.f;

    __syncthreads();

    for (int et = 0; et < TT; et++) {
        const int pb = et & 1;
        const int tn = (et + 1 < TT) ? et + 1 : et;   // clamped prefetch index

        // prefetch next W1 + next biases (overlap GEMM1)
        float4 rW1[8];
#pragma unroll
        for (int p = 0; p < 8; p++)
            rW1[p] = *(const float4*)(W1 + (size_t)tn * DD * HH + (size_t)(tid + p * 256) * 4);
        float rb1 = 0.f, rb2 = 0.f;
        if (tid < 128)      rb1 = b1[tn * HH + tid];
        else if (tid < 192) rb2 = b2[tn * DD + (tid - 128)];

        // GEMM1: h = relu(X @ W1 + b1)  (128x128, k=64)
        float hacc[2][8][4];
#pragma unroll
        for (int mi = 0; mi < 2; mi++)
#pragma unroll
            for (int ni = 0; ni < 8; ni++)
#pragma unroll
                for (int j = 0; j < 4; j++) hacc[mi][ni][j] = 0.f;
#pragma unroll
        for (int kk = 0; kk < 8; kk++) {
            uint32_t a[2][4], bf[8][2];
#pragma unroll
            for (int mi = 0; mi < 2; mi++) {
                int mr = wm + 16 * mi;
                a[mi][0] = BITS(Xs[(mr + g) * 68 + kk * 8 + t]);
                a[mi][1] = BITS(Xs[(mr + 8 + g) * 68 + kk * 8 + t]);
                a[mi][2] = BITS(Xs[(mr + g) * 68 + kk * 8 + t + 4]);
                a[mi][3] = BITS(Xs[(mr + 8 + g) * 68 + kk * 8 + t + 4]);
            }
#pragma unroll
            for (int ni = 0; ni < 8; ni++) {
                bf[ni][0] = BITS(W1s[(kk * 8 + t) * 136 + wn1 + 8 * ni + g]);
                bf[ni][1] = BITS(W1s[(kk * 8 + t + 4) * 136 + wn1 + 8 * ni + g]);
            }
#pragma unroll
            for (int mi = 0; mi < 2; mi++)
#pragma unroll
                for (int ni = 0; ni < 8; ni++) mma_tf32(hacc[mi][ni], a[mi], bf[ni]);
        }
        // bias + relu + tf32 -> Hs (own region)
#pragma unroll
        for (int mi = 0; mi < 2; mi++) {
            int r1 = wm + 16 * mi + g, r2 = r1 + 8;
#pragma unroll
            for (int ni = 0; ni < 8; ni++) {
                int c = wn1 + 8 * ni + 2 * t;
                float bx = b1s[pb * 128 + c], by = b1s[pb * 128 + c + 1];
                float h0 = fmaxf(hacc[mi][ni][0] + bx, 0.f);
                float h1 = fmaxf(hacc[mi][ni][1] + by, 0.f);
                float h2 = fmaxf(hacc[mi][ni][2] + bx, 0.f);
                float h3 = fmaxf(hacc[mi][ni][3] + by, 0.f);
                *(float2*)&Hs[r1 * 132 + c] = make_float2(
                    __uint_as_float(cvt_tf32(h0)), __uint_as_float(cvt_tf32(h1)));
                *(float2*)&Hs[r2 * 132 + c] = make_float2(
                    __uint_as_float(cvt_tf32(h2)), __uint_as_float(cvt_tf32(h3)));
            }
        }
        __syncthreads();   // Hs visible; W1s free; next-parity bias bufs free

        // commit prefetched W1(t+1) + biases(t+1); prefetch W2(t+1)
#pragma unroll
        for (int p = 0; p < 8; p++) {
            int f = tid + p * 256;
            *(float4*)&W1s[(f >> 5) * 136 + (f & 31) * 4] = cvt4_tf32(rW1[p]);
        }
        if (tid < 128)      b1s[(pb ^ 1) * 128 + tid]        = rb1;
        else if (tid < 192) b2s[(pb ^ 1) * 64 + (tid - 128)] = rb2;
        float4 rW2[8];
#pragma unroll
        for (int p = 0; p < 8; p++)
            rW2[p] = *(const float4*)(W2 + (size_t)tn * HH * DD + (size_t)(tid + p * 256) * 4);

        // GEMM2: acc2 = h @ W2  (128x64, k=128)
        float acc2[2][4][4];
#pragma unroll
        for (int mi = 0; mi < 2; mi++)
#pragma unroll
            for (int ni = 0; ni < 4; ni++)
#pragma unroll
                for (int j = 0; j < 4; j++) acc2[mi][ni][j] = 0.f;
#pragma unroll
        for (int kk = 0; kk < 16; kk++) {
            uint32_t a[2][4], bf[4][2];
#pragma unroll
            for (int mi = 0; mi < 2; mi++) {
                int mr = wm + 16 * mi;
                a[mi][0] = BITS(Hs[(mr + g) * 132 + kk * 8 + t]);
                a[mi][1] = BITS(Hs[(mr + 8 + g) * 132 + kk * 8 + t]);
                a[mi][2] = BITS(Hs[(mr + g) * 132 + kk * 8 + t + 4]);
                a[mi][3] = BITS(Hs[(mr + 8 + g) * 132 + kk * 8 + t + 4]);
            }
#pragma unroll
            for (int ni = 0; ni < 4; ni++) {
                bf[ni][0] = BITS(W2s[(kk * 8 + t) * 72 + wn2 + 8 * ni + g]);
                bf[ni][1] = BITS(W2s[(kk * 8 + t + 4) * 72 + wn2 + 8 * ni + g]);
            }
#pragma unroll
            for (int mi = 0; mi < 2; mi++)
#pragma unroll
                for (int ni = 0; ni < 4; ni++) mma_tf32(acc2[mi][ni], a[mi], bf[ni]);
        }
#pragma unroll
        for (int mi = 0; mi < 2; mi++) {
            int r1 = wm + 16 * mi + g, r2 = r1 + 8;
            float wA = wds[r1 * TT + et];
            float wB = wds[r2 * TT + et];
#pragma unroll
            for (int ni = 0; ni < 4; ni++) {
                int c = wn2 + 8 * ni + 2 * t;
                float bx = b2s[pb * 64 + c], by = b2s[pb * 64 + c + 1];
                Y[mi][ni][0] += wA * (acc2[mi][ni][0] + bx);
                Y[mi][ni][1] += wA * (acc2[mi][ni][1] + by);
                Y[mi][ni][2] += wB * (acc2[mi][ni][2] + bx);
                Y[mi][ni][3] += wB * (acc2[mi][ni][3] + by);
            }
        }
        __syncthreads();   // W2s free; Hs free

        // commit prefetched W2(t+1) (consumed after next iteration's mid-sync)
#pragma unroll
        for (int p = 0; p < 8; p++) {
            int f = tid + p * 256;
            *(float4*)&W2s[(f >> 4) * 72 + (f & 15) * 4] = cvt4_tf32(rW2[p]);
        }
    }

#pragma unroll
    for (int mi = 0; mi < 2; mi++)
#pragma unroll
        for (int ni = 0; ni < 4; ni++) {
            int r1 = row0 + wm + 16 * mi + g, r2 = r1 + 8;
            int c  = wn2 + 8 * ni + 2 * t;
            *(float2*)(g_ef + (size_t)r1 * DD + c) =
                make_float2(Y[mi][ni][0], Y[mi][ni][1]);
            *(float2*)(g_ef + (size_t)r2 * DD + c) =
                make_float2(Y[mi][ni][2], Y[mi][ni][3]);
        }
}

// ---------------------------------------------------------------------------
// K3: node_agg[b] = H[b]^T @ ef[b]  (M=512, N=64, K=1024) + concat ori
// double-buffered; Hs stride 136 (A-frags rows by t -> 8t+g), Bs stride 72
// ---------------------------------------------------------------------------
#define K3_HSZ (32 * 136)
#define K3_BSZ (32 * 72)
#define K3_BUF (K3_HSZ + K3_BSZ)
#define K3_SMEM_BYTES (2 * K3_BUF * 4)

__global__ __launch_bounds__(256) void k3_out(const float* __restrict__ H,
                                              const float* __restrict__ ori,
                                              float* __restrict__ out) {
    extern __shared__ float sm3[];

    const int b   = blockIdx.y;
    const int n0  = blockIdx.x * 128;
    const int tid = threadIdx.x;
    const int wid = tid >> 5, lane = tid & 31;
    const int g = lane >> 2, t = lane & 3;
    const int wm = (wid >> 1) * 32, wn = (wid & 1) * 32;

    const float* Hb  = H    + (size_t)b * EE * NN_;
    const float* efb = g_ef + (size_t)b * EE * DD;

    float acc[2][4][4];
#pragma unroll
    for (int mi = 0; mi < 2; mi++)
#pragma unroll
        for (int ni = 0; ni < 4; ni++)
#pragma unroll
            for (int j = 0; j < 4; j++) acc[mi][ni][j] = 0.f;

    float4 ra[4], rb[2];
#pragma unroll
    for (int p = 0; p < 4; p++) {
        int f = tid + p * 256;
        ra[p] = *(const float4*)(Hb + (size_t)(f >> 5) * NN_ + n0 + (f & 31) * 4);
    }
#pragma unroll
    for (int p = 0; p < 2; p++) {
        int f = tid + p * 256;
        rb[p] = *(const float4*)(efb + (size_t)(f >> 4) * DD + (f & 15) * 4);
    }
    {
        float* H0 = sm3; float* B0 = sm3 + K3_HSZ;
#pragma unroll
        for (int p = 0; p < 4; p++) {
            int f = tid + p * 256;
            *(float4*)&H0[(f >> 5) * 136 + (f & 31) * 4] = cvt4_tf32(ra[p]);
        }
#pragma unroll
        for (int p = 0; p < 2; p++) {
            int f = tid + p * 256;
            *(float4*)&B0[(f >> 4) * 72 + (f & 15) * 4] = cvt4_tf32(rb[p]);
        }
    }
    __syncthreads();

    int buf = 0;
    for (int e0 = 0; e0 < EE; e0 += 32) {
        const int en = e0 + 32;
        if (en < EE) {
#pragma unroll
            for (int p = 0; p < 4; p++) {
                int f = tid + p * 256;
                ra[p] = *(const float4*)(Hb + (size_t)(en + (f >> 5)) * NN_ + n0 + (f & 31) * 4);
            }
#pragma unroll
            for (int p = 0; p < 2; p++) {
                int f = tid + p * 256;
                rb[p] = *(const float4*)(efb + (size_t)(en + (f >> 4)) * DD + (f & 15) * 4);
            }
        }
        const float* H_ = sm3 + buf * K3_BUF;
        const float* B_ = H_ + K3_HSZ;
#pragma unroll
        for (int kk = 0; kk < 4; kk++) {
            uint32_t a[2][4], bf[4][2];
#pragma unroll
            for (int mi = 0; mi < 2; mi++) {
                int mr = wm + 16 * mi;   // A[m][k] = Hs[k][m]
                a[mi][0] = BITS(H_[(kk * 8 + t) * 136 + mr + g]);
                a[mi][1] = BITS(H_[(kk * 8 + t) * 136 + mr + 8 + g]);
                a[mi][2] = BITS(H_[(kk * 8 + t + 4) * 136 + mr + g]);
                a[mi][3] = BITS(H_[(kk * 8 + t + 4) * 136 + mr + 8 + g]);
            }
#pragma unroll
            for (int ni = 0; ni < 4; ni++) {
                bf[ni][0] = BITS(B_[(kk * 8 + t) * 72 + wn + 8 * ni + g]);
                bf[ni][1] = BITS(B_[(kk * 8 + t + 4) * 72 + wn + 8 * ni + g]);
            }
#pragma unroll
            for (int mi = 0; mi < 2; mi++)
#pragma unroll
                for (int ni = 0; ni < 4; ni++) mma_tf32(acc[mi][ni], a[mi], bf[ni]);
        }
        if (en < EE) {
            float* Hn = sm3 + (buf ^ 1) * K3_BUF;
            float* Bn = Hn + K3_HSZ;
#pragma unroll
            for (int p = 0; p < 4; p++) {
                int f = tid + p * 256;
                *(float4*)&Hn[(f >> 5) * 136 + (f & 31) * 4] = cvt4_tf32(ra[p]);
            }
#pragma unroll
            for (int p = 0; p < 2; p++) {
                int f = tid + p * 256;
                *(float4*)&Bn[(f >> 4) * 72 + (f & 15) * 4] = cvt4_tf32(rb[p]);
            }
        }
        __syncthreads();
        buf ^= 1;
    }

    float*       outb = out + (size_t)b * NN_ * (2 * DD);
    const float* orib = ori + (size_t)b * NN_ * DD;
#pragma unroll
    for (int mi = 0; mi < 2; mi++)
#pragma unroll
        for (int ni = 0; ni < 4; ni++) {
            int r1 = n0 + wm + 16 * mi + g, r2 = r1 + 8;
            int c  = wn + 8 * ni + 2 * t;
            *(float2*)(outb + (size_t)r1 * (2 * DD) + c) =
                make_float2(acc[mi][ni][0], acc[mi][ni][1]);
            *(float2*)(outb + (size_t)r2 * (2 * DD) + c) =
                make_float2(acc[mi][ni][2], acc[mi][ni][3]);
        }
    // concat half: copy ori rows
#pragma unroll
    for (int p = 0; p < 8; p++) {
        int f = tid + p * 256;
        int r = f >> 4, cq = f & 15;
        float4 v = *(const float4*)(orib + (size_t)(n0 + r) * DD + cq * 4);
        *(float4*)(outb + (size_t)(n0 + r) * (2 * DD) + DD + cq * 4) = v;
    }
}

// ---------------------------------------------------------------------------
extern "C" void kernel_launch(void* const* d_in, const int* in_sizes, int n_in,
                              void* d_out, int out_size) {
    const float* ed  = (const float*)d_in[0];
    const float* H   = (const float*)d_in[1];
    const float* ori = (const float*)d_in[2];
    const float* W1  = (const float*)d_in[3];
    const float* b1  = (const float*)d_in[4];
    const float* W2  = (const float*)d_in[5];
    const float* b2  = (const float*)d_in[6];
    float* out = (float*)d_out;

    cudaFuncSetAttribute(k1_edges, cudaFuncAttributeMaxDynamicSharedMemorySize,
                         K1_SMEM_BYTES);
    cudaFuncSetAttribute(k2_mlp, cudaFuncAttributeMaxDynamicSharedMemorySize,
                         K2_SMEM_BYTES);
    cudaFuncSetAttribute(k3_out, cudaFuncAttributeMaxDynamicSharedMemorySize,
                         K3_SMEM_BYTES);

    dim3 g1(EE / 128, BB);
    k1_edges<<<g1, 256, K1_SMEM_BYTES>>>(H, ori);

    k2_mlp<<<(BB * EE) / 128, 256, K2_SMEM_BYTES>>>(ed, W1, b1, W2, b2);

    dim3 g3(NN_ / 128, BB);
    k3_out<<<g3, 256, K3_SMEM_BYTES>>>(H, ori, out);
}

// round 4
// speedup vs baseline: 3.7693x; 1.4141x over previous
#include <cuda_runtime.h>
#include <cuda_fp16.h>
#include <cstdint>

#define BB 64
#define EE 1024
#define NN_ 512
#define DD 64
#define HH 128
#define TT 5

// fp16-packed scratch (word = half2), device globals — no runtime allocation
__device__ uint32_t g_eh[BB * EE * (DD / 2)];    // 8 MB: edges, row e: 32 words (d-pairs)
__device__ uint32_t g_efh[BB * EE * (DD / 2)];   // 8 MB: edge_feature, same layout

// ---------------------------------------------------------------------------
// helpers
// ---------------------------------------------------------------------------
__device__ __forceinline__ uint32_t h2(float lo, float hi) {
    __half2 h = __floats2half2_rn(lo, hi);
    return *reinterpret_cast<uint32_t*>(&h);
}
__device__ __forceinline__ void mma_fp16(float c[4], const uint32_t a[4],
                                         const uint32_t b[2]) {
    asm volatile(
        "mma.sync.aligned.m16n8k16.row.col.f32.f16.f16.f32 "
        "{%0,%1,%2,%3}, {%4,%5,%6,%7}, {%8,%9}, {%0,%1,%2,%3};"
        : "+f"(c[0]), "+f"(c[1]), "+f"(c[2]), "+f"(c[3])
        : "r"(a[0]), "r"(a[1]), "r"(a[2]), "r"(a[3]), "r"(b[0]), "r"(b[1]));
}

// ---------------------------------------------------------------------------
// K1: edges[b] = H[b] @ ori[b]  (M=1024, N=64, K=512), fp16 MMA, double-buffered
// CTA 128x64, 8 warps (4m x 2n), warp tile 32x32, K-chunk 32
// As: [m][kpair half2] stride 20 words (bank 20g+t perm)
// Bs: [kpair][n half2-over-k] stride 72 words (bank 8t+g perm)
// ---------------------------------------------------------------------------
#define K1_AW 20
#define K1_BW 72
#define K1_ASZ (128 * K1_AW)
#define K1_BSZ (16 * K1_BW)
#define K1_BUF (K1_ASZ + K1_BSZ)
#define K1_SMEM_BYTES (2 * K1_BUF * 4)

__global__ __launch_bounds__(256) void k1_edges(const float* __restrict__ H,
                                                const float* __restrict__ ori) {
    extern __shared__ uint32_t sw1[];

    const int b   = blockIdx.y;
    const int m0  = blockIdx.x * 128;
    const int tid = threadIdx.x;
    const int wid = tid >> 5, lane = tid & 31;
    const int g = lane >> 2, t = lane & 3;
    const int wm = (wid >> 1) * 32, wn = (wid & 1) * 32;

    const float* Hb   = H   + (size_t)b * EE * NN_;
    const float* orib = ori + (size_t)b * NN_ * DD;

    float acc[2][4][4];
#pragma unroll
    for (int mi = 0; mi < 2; mi++)
#pragma unroll
        for (int ni = 0; ni < 4; ni++)
#pragma unroll
            for (int j = 0; j < 4; j++) acc[mi][ni][j] = 0.f;

    // staging thread roles
    const int ar = tid >> 3, akq = tid & 7;      // A: 4 slots/thread via +p*256
    const int br = tid >> 4, bcq = tid & 15;     // B: 1 slot/thread, 2 rows

    float4 ra[4], rb0, rb1;
#pragma unroll
    for (int p = 0; p < 4; p++) {
        int f = tid + p * 256;
        ra[p] = *(const float4*)(Hb + (size_t)(m0 + (f >> 3)) * NN_ + (f & 7) * 4);
    }
    rb0 = *(const float4*)(orib + (size_t)(2 * br) * DD + bcq * 4);
    rb1 = *(const float4*)(orib + (size_t)(2 * br + 1) * DD + bcq * 4);
    {
        uint32_t* A0 = sw1; uint32_t* B0 = sw1 + K1_ASZ;
#pragma unroll
        for (int p = 0; p < 4; p++) {
            int f = tid + p * 256;
            uint2 w; w.x = h2(ra[p].x, ra[p].y); w.y = h2(ra[p].z, ra[p].w);
            *(uint2*)&A0[(f >> 3) * K1_AW + (f & 7) * 2] = w;
        }
        uint4 w;
        w.x = h2(rb0.x, rb1.x); w.y = h2(rb0.y, rb1.y);
        w.z = h2(rb0.z, rb1.z); w.w = h2(rb0.w, rb1.w);
        *(uint4*)&B0[br * K1_BW + bcq * 4] = w;
    }
    __syncthreads();

    int buf = 0;
    for (int k0 = 0; k0 < NN_; k0 += 32) {
        const int kn = k0 + 32;
        if (kn < NN_) {
#pragma unroll
            for (int p = 0; p < 4; p++) {
                int f = tid + p * 256;
                ra[p] = *(const float4*)(Hb + (size_t)(m0 + (f >> 3)) * NN_ + kn + (f & 7) * 4);
            }
            rb0 = *(const float4*)(orib + (size_t)(kn + 2 * br) * DD + bcq * 4);
            rb1 = *(const float4*)(orib + (size_t)(kn + 2 * br + 1) * DD + bcq * 4);
        }
        const uint32_t* A_ = sw1 + buf * K1_BUF;
        const uint32_t* B_ = A_ + K1_ASZ;
#pragma unroll
        for (int kk = 0; kk < 2; kk++) {
            uint32_t a[2][4], bf[4][2];
#pragma unroll
            for (int mi = 0; mi < 2; mi++) {
                int mr = wm + 16 * mi;
                a[mi][0] = A_[(mr + g) * K1_AW + 8 * kk + t];
                a[mi][1] = A_[(mr + 8 + g) * K1_AW + 8 * kk + t];
                a[mi][2] = A_[(mr + g) * K1_AW + 8 * kk + t + 4];
                a[mi][3] = A_[(mr + 8 + g) * K1_AW + 8 * kk + t + 4];
            }
#pragma unroll
            for (int ni = 0; ni < 4; ni++) {
                bf[ni][0] = B_[(8 * kk + t) * K1_BW + wn + 8 * ni + g];
                bf[ni][1] = B_[(8 * kk + t + 4) * K1_BW + wn + 8 * ni + g];
            }
#pragma unroll
            for (int mi = 0; mi < 2; mi++)
#pragma unroll
                for (int ni = 0; ni < 4; ni++) mma_fp16(acc[mi][ni], a[mi], bf[ni]);
        }
        if (kn < NN_) {
            uint32_t* An = sw1 + (buf ^ 1) * K1_BUF;
            uint32_t* Bn = An + K1_ASZ;
#pragma unroll
            for (int p = 0; p < 4; p++) {
                int f = tid + p * 256;
                uint2 w; w.x = h2(ra[p].x, ra[p].y); w.y = h2(ra[p].z, ra[p].w);
                *(uint2*)&An[(f >> 3) * K1_AW + (f & 7) * 2] = w;
            }
            uint4 w;
            w.x = h2(rb0.x, rb1.x); w.y = h2(rb0.y, rb1.y);
            w.z = h2(rb0.z, rb1.z); w.w = h2(rb0.w, rb1.w);
            *(uint4*)&Bn[br * K1_BW + bcq * 4] = w;
        }
        __syncthreads();
        buf ^= 1;
    }

    // epilogue: pack fp32 acc -> half2 words into g_eh
    const size_t rowbase = (size_t)b * EE;
#pragma unroll
    for (int mi = 0; mi < 2; mi++)
#pragma unroll
        for (int ni = 0; ni < 4; ni++) {
            int r1 = m0 + wm + 16 * mi + g, r2 = r1 + 8;
            int cw = (wn >> 1) + 4 * ni + t;
            g_eh[(rowbase + r1) * 32 + cw] = h2(acc[mi][ni][0], acc[mi][ni][1]);
            g_eh[(rowbase + r2) * 32 + cw] = h2(acc[mi][ni][2], acc[mi][ni][3]);
        }
}

// ---------------------------------------------------------------------------
// K2: per-edge mixture MLP, fp16 MMA, weight prefetch across type loop
// Xs [128][36w], W1s [32kp][136w], Hs [128][68w], W2s [64kp][72w]
// ---------------------------------------------------------------------------
#define K2_XS_W  (128 * 36)
#define K2_W1_W  (32 * 136)
#define K2_HS_W  (128 * 68)
#define K2_W2_W  (64 * 72)
#define K2_TILE_W (K2_XS_W + K2_W1_W + K2_HS_W + K2_W2_W)
#define K2_SMEM_BYTES ((K2_TILE_W + 640 + 256 + 128) * 4)

__global__ __launch_bounds__(256) void k2_mlp(const float* __restrict__ ed,
                                              const float* __restrict__ W1,
                                              const float* __restrict__ b1,
                                              const float* __restrict__ W2,
                                              const float* __restrict__ b2) {
    extern __shared__ uint32_t smw[];
    uint32_t* Xs  = smw;
    uint32_t* W1s = Xs + K2_XS_W;
    uint32_t* Hs  = W1s + K2_W1_W;
    uint32_t* W2s = Hs + K2_HS_W;
    float* wds = (float*)(W2s + K2_W2_W);     // [128][5]
    float* b1s = wds + 640;                   // [2][128]
    float* b2s = b1s + 256;                   // [2][64]

    const int row0 = blockIdx.x * 128;
    const int tid  = threadIdx.x;
    const int wid  = tid >> 5, lane = tid & 31;
    const int g = lane >> 2, t = lane & 3;
    const int wm  = (wid >> 1) * 32;
    const int wn1 = (wid & 1) * 64;           // GEMM1 n-offset (elements)
    const int wn2 = (wid & 1) * 32;           // GEMM2 n-offset (elements)

    // stage X directly from packed fp16 edges (no cvt)
#pragma unroll
    for (int p = 0; p < 4; p++) {
        int s = tid + p * 256;
        int r = s >> 3, cq = s & 7;
        uint4 v = *(const uint4*)&g_eh[((size_t)row0 + r) * 32 + cq * 4];
        *(uint4*)&Xs[r * 36 + cq * 4] = v;
    }
    for (int f = tid; f < 640; f += 256) wds[f] = ed[(size_t)row0 * TT + f];

    // stage type-0 weights (B-pack: half2 over k-pairs) + biases
#pragma unroll
    for (int p = 0; p < 4; p++) {
        int s = tid + p * 256;
        {   // W1: [64][128] -> 32 kpairs x 32 float4-cols
            int r = s >> 5, cq = s & 31;
            float4 f0 = *(const float4*)(W1 + (size_t)(2 * r) * HH + cq * 4);
            float4 f1 = *(const float4*)(W1 + (size_t)(2 * r + 1) * HH + cq * 4);
            uint4 w;
            w.x = h2(f0.x, f1.x); w.y = h2(f0.y, f1.y);
            w.z = h2(f0.z, f1.z); w.w = h2(f0.w, f1.w);
            *(uint4*)&W1s[r * 136 + cq * 4] = w;
        }
        {   // W2: [128][64] -> 64 kpairs x 16 float4-cols
            int r = s >> 4, cq = s & 15;
            float4 f0 = *(const float4*)(W2 + (size_t)(2 * r) * DD + cq * 4);
            float4 f1 = *(const float4*)(W2 + (size_t)(2 * r + 1) * DD + cq * 4);
            uint4 w;
            w.x = h2(f0.x, f1.x); w.y = h2(f0.y, f1.y);
            w.z = h2(f0.z, f1.z); w.w = h2(f0.w, f1.w);
            *(uint4*)&W2s[r * 72 + cq * 4] = w;
        }
    }
    if (tid < 128)      b1s[tid]       = b1[tid];
    else if (tid < 192) b2s[tid - 128] = b2[tid - 128];

    float Y[2][4][4];
#pragma unroll
    for (int mi = 0; mi < 2; mi++)
#pragma unroll
        for (int ni = 0; ni < 4; ni++)
#pragma unroll
            for (int j = 0; j < 4; j++) Y[mi][ni][j] = 0.f;

    __syncthreads();

    for (int et = 0; et < TT; et++) {
        const int pb = et & 1;
        const int tn = (et + 1 < TT) ? et + 1 : et;

        // prefetch next W1 + biases (overlaps GEMM1)
        float4 rW1a[4], rW1b[4];
#pragma unroll
        for (int p = 0; p < 4; p++) {
            int s = tid + p * 256;
            int r = s >> 5, cq = s & 31;
            rW1a[p] = *(const float4*)(W1 + (size_t)tn * DD * HH + (size_t)(2 * r) * HH + cq * 4);
            rW1b[p] = *(const float4*)(W1 + (size_t)tn * DD * HH + (size_t)(2 * r + 1) * HH + cq * 4);
        }
        float rb1 = 0.f, rb2 = 0.f;
        if (tid < 128)      rb1 = b1[tn * HH + tid];
        else if (tid < 192) rb2 = b2[tn * DD + (tid - 128)];

        // GEMM1: h = relu(X @ W1 + b1)  (128x128, k=64 -> 4 kk chunks)
        float hacc[2][8][4];
#pragma unroll
        for (int mi = 0; mi < 2; mi++)
#pragma unroll
            for (int ni = 0; ni < 8; ni++)
#pragma unroll
                for (int j = 0; j < 4; j++) hacc[mi][ni][j] = 0.f;
#pragma unroll
        for (int kk = 0; kk < 4; kk++) {
            uint32_t a[2][4], bf[8][2];
#pragma unroll
            for (int mi = 0; mi < 2; mi++) {
                int mr = wm + 16 * mi;
                a[mi][0] = Xs[(mr + g) * 36 + 8 * kk + t];
                a[mi][1] = Xs[(mr + 8 + g) * 36 + 8 * kk + t];
                a[mi][2] = Xs[(mr + g) * 36 + 8 * kk + t + 4];
                a[mi][3] = Xs[(mr + 8 + g) * 36 + 8 * kk + t + 4];
            }
#pragma unroll
            for (int ni = 0; ni < 8; ni++) {
                bf[ni][0] = W1s[(8 * kk + t) * 136 + wn1 + 8 * ni + g];
                bf[ni][1] = W1s[(8 * kk + t + 4) * 136 + wn1 + 8 * ni + g];
            }
#pragma unroll
            for (int mi = 0; mi < 2; mi++)
#pragma unroll
                for (int ni = 0; ni < 8; ni++) mma_fp16(hacc[mi][ni], a[mi], bf[ni]);
        }
        // bias + relu -> Hs (fp16 A-layout, pairs along k)
        const int wn1h = wn1 >> 1;
#pragma unroll
        for (int mi = 0; mi < 2; mi++) {
            int r1 = wm + 16 * mi + g, r2 = r1 + 8;
#pragma unroll
            for (int ni = 0; ni < 8; ni++) {
                int c = wn1 + 8 * ni + 2 * t;
                float bx = b1s[pb * 128 + c], by = b1s[pb * 128 + c + 1];
                Hs[r1 * 68 + wn1h + 4 * ni + t] =
                    h2(fmaxf(hacc[mi][ni][0] + bx, 0.f), fmaxf(hacc[mi][ni][1] + by, 0.f));
                Hs[r2 * 68 + wn1h + 4 * ni + t] =
                    h2(fmaxf(hacc[mi][ni][2] + bx, 0.f), fmaxf(hacc[mi][ni][3] + by, 0.f));
            }
        }
        __syncthreads();   // Hs visible; W1s free; next-parity biases free

        // commit prefetched W1(t+1)+biases; prefetch W2(t+1)
#pragma unroll
        for (int p = 0; p < 4; p++) {
            int s = tid + p * 256;
            int r = s >> 5, cq = s & 31;
            uint4 w;
            w.x = h2(rW1a[p].x, rW1b[p].x); w.y = h2(rW1a[p].y, rW1b[p].y);
            w.z = h2(rW1a[p].z, rW1b[p].z); w.w = h2(rW1a[p].w, rW1b[p].w);
            *(uint4*)&W1s[r * 136 + cq * 4] = w;
        }
        if (tid < 128)      b1s[(pb ^ 1) * 128 + tid]        = rb1;
        else if (tid < 192) b2s[(pb ^ 1) * 64 + (tid - 128)] = rb2;
        float4 rW2a[4], rW2b[4];
#pragma unroll
        for (int p = 0; p < 4; p++) {
            int s = tid + p * 256;
            int r = s >> 4, cq = s & 15;
            rW2a[p] = *(const float4*)(W2 + (size_t)tn * HH * DD + (size_t)(2 * r) * DD + cq * 4);
            rW2b[p] = *(const float4*)(W2 + (size_t)tn * HH * DD + (size_t)(2 * r + 1) * DD + cq * 4);
        }

        // GEMM2: acc2 = h @ W2  (128x64, k=128 -> 8 kk chunks)
        float acc2[2][4][4];
#pragma unroll
        for (int mi = 0; mi < 2; mi++)
#pragma unroll
            for (int ni = 0; ni < 4; ni++)
#pragma unroll
                for (int j = 0; j < 4; j++) acc2[mi][ni][j] = 0.f;
#pragma unroll
        for (int kk = 0; kk < 8; kk++) {
            uint32_t a[2][4], bf[4][2];
#pragma unroll
            for (int mi = 0; mi < 2; mi++) {
                int mr = wm + 16 * mi;
                a[mi][0] = Hs[(mr + g) * 68 + 8 * kk + t];
                a[mi][1] = Hs[(mr + 8 + g) * 68 + 8 * kk + t];
                a[mi][2] = Hs[(mr + g) * 68 + 8 * kk + t + 4];
                a[mi][3] = Hs[(mr + 8 + g) * 68 + 8 * kk + t + 4];
            }
#pragma unroll
            for (int ni = 0; ni < 4; ni++) {
                bf[ni][0] = W2s[(8 * kk + t) * 72 + wn2 + 8 * ni + g];
                bf[ni][1] = W2s[(8 * kk + t + 4) * 72 + wn2 + 8 * ni + g];
            }
#pragma unroll
            for (int mi = 0; mi < 2; mi++)
#pragma unroll
                for (int ni = 0; ni < 4; ni++) mma_fp16(acc2[mi][ni], a[mi], bf[ni]);
        }
#pragma unroll
        for (int mi = 0; mi < 2; mi++) {
            int r1 = wm + 16 * mi + g, r2 = r1 + 8;
            float wA = wds[r1 * TT + et];
            float wB = wds[r2 * TT + et];
#pragma unroll
            for (int ni = 0; ni < 4; ni++) {
                int c = wn2 + 8 * ni + 2 * t;
                float bx = b2s[pb * 64 + c], by = b2s[pb * 64 + c + 1];
                Y[mi][ni][0] += wA * (acc2[mi][ni][0] + bx);
                Y[mi][ni][1] += wA * (acc2[mi][ni][1] + by);
                Y[mi][ni][2] += wB * (acc2[mi][ni][2] + bx);
                Y[mi][ni][3] += wB * (acc2[mi][ni][3] + by);
            }
        }
        __syncthreads();   // W2s free; Hs free

        // commit prefetched W2(t+1)
#pragma unroll
        for (int p = 0; p < 4; p++) {
            int s = tid + p * 256;
            int r = s >> 4, cq = s & 15;
            uint4 w;
            w.x = h2(rW2a[p].x, rW2b[p].x); w.y = h2(rW2a[p].y, rW2b[p].y);
            w.z = h2(rW2a[p].z, rW2b[p].z); w.w = h2(rW2a[p].w, rW2b[p].w);
            *(uint4*)&W2s[r * 72 + cq * 4] = w;
        }
    }

    // epilogue: pack Y -> half2 words into g_efh
    const int wn2h = wn2 >> 1;
#pragma unroll
    for (int mi = 0; mi < 2; mi++)
#pragma unroll
        for (int ni = 0; ni < 4; ni++) {
            int r1 = row0 + wm + 16 * mi + g, r2 = r1 + 8;
            int cw = wn2h + 4 * ni + t;
            g_efh[(size_t)r1 * 32 + cw] = h2(Y[mi][ni][0], Y[mi][ni][1]);
            g_efh[(size_t)r2 * 32 + cw] = h2(Y[mi][ni][2], Y[mi][ni][3]);
        }
}

// ---------------------------------------------------------------------------
// K3: node_agg[b] = H[b]^T @ ef[b]  (M=512, N=64, K=1024) + concat ori
// Hp: [kpair][m] stride 136w (A transposed, pairs over k); Bs: [kpair][d] 72w
// ---------------------------------------------------------------------------
#define K3_HW 136
#define K3_BW 72
#define K3_HSZ (16 * K3_HW)
#define K3_BSZ (16 * K3_BW)
#define K3_BUF (K3_HSZ + K3_BSZ)
#define K3_SMEM_BYTES (2 * K3_BUF * 4)

__global__ __launch_bounds__(256) void k3_out(const float* __restrict__ H,
                                              const float* __restrict__ ori,
                                              float* __restrict__ out) {
    extern __shared__ uint32_t sw3[];

    const int b   = blockIdx.y;
    const int n0  = blockIdx.x * 128;
    const int tid = threadIdx.x;
    const int wid = tid >> 5, lane = tid & 31;
    const int g = lane >> 2, t = lane & 3;
    const int wm = (wid >> 1) * 32, wn = (wid & 1) * 32;

    const float* Hb = H + (size_t)b * EE * NN_;
    const uint32_t* efb = g_efh + (size_t)b * EE * 32;

    float acc[2][4][4];
#pragma unroll
    for (int mi = 0; mi < 2; mi++)
#pragma unroll
        for (int ni = 0; ni < 4; ni++)
#pragma unroll
            for (int j = 0; j < 4; j++) acc[mi][ni][j] = 0.f;

    const int br = tid >> 4, bcq = tid & 15;   // Bs: 1 slot/thread

    float4 ha0[2], ha1[2];
    uint2 eb0, eb1;
#pragma unroll
    for (int p = 0; p < 2; p++) {
        int s = tid + p * 256;
        int r = s >> 5, cq = s & 31;
        ha0[p] = *(const float4*)(Hb + (size_t)(2 * r) * NN_ + n0 + cq * 4);
        ha1[p] = *(const float4*)(Hb + (size_t)(2 * r + 1) * NN_ + n0 + cq * 4);
    }
    eb0 = *(const uint2*)&efb[(size_t)(2 * br) * 32 + bcq * 2];
    eb1 = *(const uint2*)&efb[(size_t)(2 * br + 1) * 32 + bcq * 2];
    {
        uint32_t* Hp = sw3; uint32_t* Bp = sw3 + K3_HSZ;
#pragma unroll
        for (int p = 0; p < 2; p++) {
            int s = tid + p * 256;
            int r = s >> 5, cq = s & 31;
            uint4 w;
            w.x = h2(ha0[p].x, ha1[p].x); w.y = h2(ha0[p].y, ha1[p].y);
            w.z = h2(ha0[p].z, ha1[p].z); w.w = h2(ha0[p].w, ha1[p].w);
            *(uint4*)&Hp[r * K3_HW + cq * 4] = w;
        }
        uint4 w;
        w.x = __byte_perm(eb0.x, eb1.x, 0x5410);
        w.y = __byte_perm(eb0.x, eb1.x, 0x7632);
        w.z = __byte_perm(eb0.y, eb1.y, 0x5410);
        w.w = __byte_perm(eb0.y, eb1.y, 0x7632);
        *(uint4*)&Bp[br * K3_BW + bcq * 4] = w;
    }
    __syncthreads();

    int buf = 0;
    for (int e0 = 0; e0 < EE; e0 += 32) {
        const int en = e0 + 32;
        if (en < EE) {
#pragma unroll
            for (int p = 0; p < 2; p++) {
                int s = tid + p * 256;
                int r = s >> 5, cq = s & 31;
                ha0[p] = *(const float4*)(Hb + (size_t)(en + 2 * r) * NN_ + n0 + cq * 4);
                ha1[p] = *(const float4*)(Hb + (size_t)(en + 2 * r + 1) * NN_ + n0 + cq * 4);
            }
            eb0 = *(const uint2*)&efb[(size_t)(en + 2 * br) * 32 + bcq * 2];
            eb1 = *(const uint2*)&efb[(size_t)(en + 2 * br + 1) * 32 + bcq * 2];
        }
        const uint32_t* Hp = sw3 + buf * K3_BUF;
        const uint32_t* Bp = Hp + K3_HSZ;
#pragma unroll
        for (int kk = 0; kk < 2; kk++) {
            uint32_t a[2][4], bf[4][2];
#pragma unroll
            for (int mi = 0; mi < 2; mi++) {
                int mr = wm + 16 * mi;   // A[m][k] = H[k][m] -> Hp[kpair][m]
                a[mi][0] = Hp[(8 * kk + t) * K3_HW + mr + g];
                a[mi][1] = Hp[(8 * kk + t) * K3_HW + mr + 8 + g];
                a[mi][2] = Hp[(8 * kk + t + 4) * K3_HW + mr + g];
                a[mi][3] = Hp[(8 * kk + t + 4) * K3_HW + mr + 8 + g];
            }
#pragma unroll
            for (int ni = 0; ni < 4; ni++) {
                bf[ni][0] = Bp[(8 * kk + t) * K3_BW + wn + 8 * ni + g];
                bf[ni][1] = Bp[(8 * kk + t + 4) * K3_BW + wn + 8 * ni + g];
            }
#pragma unroll
            for (int mi = 0; mi < 2; mi++)
#pragma unroll
                for (int ni = 0; ni < 4; ni++) mma_fp16(acc[mi][ni], a[mi], bf[ni]);
        }
        if (en < EE) {
            uint32_t* Hn = sw3 + (buf ^ 1) * K3_BUF;
            uint32_t* Bn = Hn + K3_HSZ;
#pragma unroll
            for (int p = 0; p < 2; p++) {
                int s = tid + p * 256;
                int r = s >> 5, cq = s & 31;
                uint4 w;
                w.x = h2(ha0[p].x, ha1[p].x); w.y = h2(ha0[p].y, ha1[p].y);
                w.z = h2(ha0[p].z, ha1[p].z); w.w = h2(ha0[p].w, ha1[p].w);
                *(uint4*)&Hn[r * K3_HW + cq * 4] = w;
            }
            uint4 w;
            w.x = __byte_perm(eb0.x, eb1.x, 0x5410);
            w.y = __byte_perm(eb0.x, eb1.x, 0x7632);
            w.z = __byte_perm(eb0.y, eb1.y, 0x5410);
            w.w = __byte_perm(eb0.y, eb1.y, 0x7632);
            *(uint4*)&Bn[br * K3_BW + bcq * 4] = w;
        }
        __syncthreads();
        buf ^= 1;
    }

    float*       outb = out + (size_t)b * NN_ * (2 * DD);
    const float* orib = ori + (size_t)b * NN_ * DD;
#pragma unroll
    for (int mi = 0; mi < 2; mi++)
#pragma unroll
        for (int ni = 0; ni < 4; ni++) {
            int r1 = n0 + wm + 16 * mi + g, r2 = r1 + 8;
            int c  = wn + 8 * ni + 2 * t;
            *(float2*)(outb + (size_t)r1 * (2 * DD) + c) =
                make_float2(acc[mi][ni][0], acc[mi][ni][1]);
            *(float2*)(outb + (size_t)r2 * (2 * DD) + c) =
                make_float2(acc[mi][ni][2], acc[mi][ni][3]);
        }
    // concat half: copy ori rows
#pragma unroll
    for (int p = 0; p < 8; p++) {
        int f = tid + p * 256;
        int r = f >> 4, cq = f & 15;
        float4 v = *(const float4*)(orib + (size_t)(n0 + r) * DD + cq * 4);
        *(float4*)(outb + (size_t)(n0 + r) * (2 * DD) + DD + cq * 4) = v;
    }
}

// ---------------------------------------------------------------------------
extern "C" void kernel_launch(void* const* d_in, const int* in_sizes, int n_in,
                              void* d_out, int out_size) {
    const float* ed  = (const float*)d_in[0];
    const float* H   = (const float*)d_in[1];
    const float* ori = (const float*)d_in[2];
    const float* W1  = (const float*)d_in[3];
    const float* b1  = (const float*)d_in[4];
    const float* W2  = (const float*)d_in[5];
    const float* b2  = (const float*)d_in[6];
    float* out = (float*)d_out;

    cudaFuncSetAttribute(k2_mlp, cudaFuncAttributeMaxDynamicSharedMemorySize,
                         K2_SMEM_BYTES);

    dim3 g1(EE / 128, BB);
    k1_edges<<<g1, 256, K1_SMEM_BYTES>>>(H, ori);

    k2_mlp<<<(BB * EE) / 128, 256, K2_SMEM_BYTES>>>(ed, W1, b1, W2, b2);

    dim3 g3(NN_ / 128, BB);
    k3_out<<<g3, 256, K3_SMEM_BYTES>>>(H, ori, out);
}

// round 5
// speedup vs baseline: 4.0528x; 1.0752x over previous
#include <cuda_runtime.h>
#include <cuda_fp16.h>
#include <cstdint>

#define BB 64
#define EE 1024
#define NN_ 512
#define DD 64
#define HH 128
#define TT 5

// fp16-packed scratch (word = half2): edge_feature only (edges stay in smem now)
__device__ uint32_t g_efh[BB * EE * (DD / 2)];   // 8 MB

// ---------------------------------------------------------------------------
// helpers
// ---------------------------------------------------------------------------
__device__ __forceinline__ uint32_t h2(float lo, float hi) {
    __half2 h = __floats2half2_rn(lo, hi);
    return *reinterpret_cast<uint32_t*>(&h);
}
__device__ __forceinline__ void mma_fp16(float c[4], const uint32_t a[4],
                                         const uint32_t b[2]) {
    asm volatile(
        "mma.sync.aligned.m16n8k16.row.col.f32.f16.f16.f32 "
        "{%0,%1,%2,%3}, {%4,%5,%6,%7}, {%8,%9}, {%0,%1,%2,%3};"
        : "+f"(c[0]), "+f"(c[1]), "+f"(c[2]), "+f"(c[3])
        : "r"(a[0]), "r"(a[1]), "r"(a[2]), "r"(a[3]), "r"(b[0]), "r"(b[1]));
}

// ---------------------------------------------------------------------------
// KF: fused K1 (edges = H @ ori) + K2 (per-type MLP mixture)
// One CTA = 128 edge rows of one batch. Edges pass phase1 -> phase2 via smem.
//
// smem (words): [Xs 128x36 persistent][region: K1 double-buffer | K2 tiles]
//   K1: A[128][20w] + B[16][72w], x2 buffers                (7424 w)
//   K2: W1s[32][136w] + Hs[128][68w] + W2s[64][72w] + f32 tail (18688 w)
// ---------------------------------------------------------------------------
#define XS_W    (128 * 36)
#define K1_AW 20
#define K1_BW 72
#define K1_ASZ (128 * K1_AW)
#define K1_BSZ (16 * K1_BW)
#define K1_BUF (K1_ASZ + K1_BSZ)
#define K2_W1_W (32 * 136)
#define K2_HS_W (128 * 68)
#define K2_W2_W (64 * 72)
#define K2_REGION_W (K2_W1_W + K2_HS_W + K2_W2_W + 640 + 256 + 128)
#define KF_REGION_W (K2_REGION_W > 2 * K1_BUF ? K2_REGION_W : 2 * K1_BUF)
#define KF_SMEM_BYTES ((XS_W + KF_REGION_W) * 4)

__global__ __launch_bounds__(256, 2) void kf_fused(
    const float* __restrict__ H,  const float* __restrict__ ori,
    const float* __restrict__ ed, const float* __restrict__ W1,
    const float* __restrict__ b1, const float* __restrict__ W2,
    const float* __restrict__ b2) {
    extern __shared__ uint32_t smw[];
    uint32_t* Xs     = smw;          // [128][36w] persistent
    uint32_t* region = smw + XS_W;

    const int b    = blockIdx.x >> 3;          // EE/128 = 8 tiles per batch
    const int m0   = (blockIdx.x & 7) * 128;
    const size_t row0 = (size_t)blockIdx.x * 128;   // flat edge-row base
    const int tid  = threadIdx.x;
    const int wid  = tid >> 5, lane = tid & 31;
    const int g = lane >> 2, t = lane & 3;
    const int wm = (wid >> 1) * 32, wn = (wid & 1) * 32;

    // ================= phase 1: edges tile = H[b] tile @ ori[b] =============
    {
        const float* Hb   = H   + (size_t)b * EE * NN_;
        const float* orib = ori + (size_t)b * NN_ * DD;

        float acc[2][4][4];
#pragma unroll
        for (int mi = 0; mi < 2; mi++)
#pragma unroll
            for (int ni = 0; ni < 4; ni++)
#pragma unroll
                for (int j = 0; j < 4; j++) acc[mi][ni][j] = 0.f;

        const int br = tid >> 4, bcq = tid & 15;

        float4 ra[4], rb0, rb1;
#pragma unroll
        for (int p = 0; p < 4; p++) {
            int f = tid + p * 256;
            ra[p] = *(const float4*)(Hb + (size_t)(m0 + (f >> 3)) * NN_ + (f & 7) * 4);
        }
        rb0 = *(const float4*)(orib + (size_t)(2 * br) * DD + bcq * 4);
        rb1 = *(const float4*)(orib + (size_t)(2 * br + 1) * DD + bcq * 4);
        {
            uint32_t* A0 = region; uint32_t* B0 = region + K1_ASZ;
#pragma unroll
            for (int p = 0; p < 4; p++) {
                int f = tid + p * 256;
                uint2 w; w.x = h2(ra[p].x, ra[p].y); w.y = h2(ra[p].z, ra[p].w);
                *(uint2*)&A0[(f >> 3) * K1_AW + (f & 7) * 2] = w;
            }
            uint4 w;
            w.x = h2(rb0.x, rb1.x); w.y = h2(rb0.y, rb1.y);
            w.z = h2(rb0.z, rb1.z); w.w = h2(rb0.w, rb1.w);
            *(uint4*)&B0[br * K1_BW + bcq * 4] = w;
        }
        __syncthreads();

        int buf = 0;
        for (int k0 = 0; k0 < NN_; k0 += 32) {
            const int kn = k0 + 32;
            if (kn < NN_) {
#pragma unroll
                for (int p = 0; p < 4; p++) {
                    int f = tid + p * 256;
                    ra[p] = *(const float4*)(Hb + (size_t)(m0 + (f >> 3)) * NN_ + kn + (f & 7) * 4);
                }
                rb0 = *(const float4*)(orib + (size_t)(kn + 2 * br) * DD + bcq * 4);
                rb1 = *(const float4*)(orib + (size_t)(kn + 2 * br + 1) * DD + bcq * 4);
            }
            const uint32_t* A_ = region + buf * K1_BUF;
            const uint32_t* B_ = A_ + K1_ASZ;
#pragma unroll
            for (int kk = 0; kk < 2; kk++) {
                uint32_t a[2][4], bf[4][2];
#pragma unroll
                for (int mi = 0; mi < 2; mi++) {
                    int mr = wm + 16 * mi;
                    a[mi][0] = A_[(mr + g) * K1_AW + 8 * kk + t];
                    a[mi][1] = A_[(mr + 8 + g) * K1_AW + 8 * kk + t];
                    a[mi][2] = A_[(mr + g) * K1_AW + 8 * kk + t + 4];
                    a[mi][3] = A_[(mr + 8 + g) * K1_AW + 8 * kk + t + 4];
                }
#pragma unroll
                for (int ni = 0; ni < 4; ni++) {
                    bf[ni][0] = B_[(8 * kk + t) * K1_BW + wn + 8 * ni + g];
                    bf[ni][1] = B_[(8 * kk + t + 4) * K1_BW + wn + 8 * ni + g];
                }
#pragma unroll
                for (int mi = 0; mi < 2; mi++)
#pragma unroll
                    for (int ni = 0; ni < 4; ni++) mma_fp16(acc[mi][ni], a[mi], bf[ni]);
            }
            if (kn < NN_) {
                uint32_t* An = region + (buf ^ 1) * K1_BUF;
                uint32_t* Bn = An + K1_ASZ;
#pragma unroll
                for (int p = 0; p < 4; p++) {
                    int f = tid + p * 256;
                    uint2 w; w.x = h2(ra[p].x, ra[p].y); w.y = h2(ra[p].z, ra[p].w);
                    *(uint2*)&An[(f >> 3) * K1_AW + (f & 7) * 2] = w;
                }
                uint4 w;
                w.x = h2(rb0.x, rb1.x); w.y = h2(rb0.y, rb1.y);
                w.z = h2(rb0.z, rb1.z); w.w = h2(rb0.w, rb1.w);
                *(uint4*)&Bn[br * K1_BW + bcq * 4] = w;
            }
            __syncthreads();
            buf ^= 1;
        }

        // epilogue: pack acc -> Xs (A-layout for GEMM1, k-dim = d pairs)
#pragma unroll
        for (int mi = 0; mi < 2; mi++)
#pragma unroll
            for (int ni = 0; ni < 4; ni++) {
                int r1 = wm + 16 * mi + g, r2 = r1 + 8;
                int cw = (wn >> 1) + 4 * ni + t;
                Xs[r1 * 36 + cw] = h2(acc[mi][ni][0], acc[mi][ni][1]);
                Xs[r2 * 36 + cw] = h2(acc[mi][ni][2], acc[mi][ni][3]);
            }
    }
    // Xs written; K1 buffers dead. Stage K2 tiles (overwrites region), then sync.
    uint32_t* W1s = region;
    uint32_t* Hs  = W1s + K2_W1_W;
    uint32_t* W2s = Hs + K2_HS_W;
    float* wds = (float*)(W2s + K2_W2_W);     // [128][5]
    float* b1s = wds + 640;                   // [2][128]
    float* b2s = b1s + 256;                   // [2][64]

    const int wn1 = (wid & 1) * 64;
    const int wn2 = (wid & 1) * 32;

    for (int f = tid; f < 640; f += 256) wds[f] = ed[row0 * TT + f];
#pragma unroll
    for (int p = 0; p < 4; p++) {
        int s = tid + p * 256;
        {   // W1 type 0: [64][128] -> 32 kpairs x 32 f4-cols
            int r = s >> 5, cq = s & 31;
            float4 f0 = *(const float4*)(W1 + (size_t)(2 * r) * HH + cq * 4);
            float4 f1 = *(const float4*)(W1 + (size_t)(2 * r + 1) * HH + cq * 4);
            uint4 w;
            w.x = h2(f0.x, f1.x); w.y = h2(f0.y, f1.y);
            w.z = h2(f0.z, f1.z); w.w = h2(f0.w, f1.w);
            *(uint4*)&W1s[r * 136 + cq * 4] = w;
        }
        {   // W2 type 0: [128][64] -> 64 kpairs x 16 f4-cols
            int r = s >> 4, cq = s & 15;
            float4 f0 = *(const float4*)(W2 + (size_t)(2 * r) * DD + cq * 4);
            float4 f1 = *(const float4*)(W2 + (size_t)(2 * r + 1) * DD + cq * 4);
            uint4 w;
            w.x = h2(f0.x, f1.x); w.y = h2(f0.y, f1.y);
            w.z = h2(f0.z, f1.z); w.w = h2(f0.w, f1.w);
            *(uint4*)&W2s[r * 72 + cq * 4] = w;
        }
    }
    if (tid < 128)      b1s[tid]       = b1[tid];
    else if (tid < 192) b2s[tid - 128] = b2[tid - 128];

    float Y[2][4][4];
#pragma unroll
    for (int mi = 0; mi < 2; mi++)
#pragma unroll
        for (int ni = 0; ni < 4; ni++)
#pragma unroll
            for (int j = 0; j < 4; j++) Y[mi][ni][j] = 0.f;

    __syncthreads();

    // ================= phase 2: 5-type MLP mixture ===========================
    for (int et = 0; et < TT; et++) {
        const int pb = et & 1;
        const int tn = (et + 1 < TT) ? et + 1 : et;

        // prefetch next W1 + biases (overlaps GEMM1)
        float4 rW1a[4], rW1b[4];
#pragma unroll
        for (int p = 0; p < 4; p++) {
            int s = tid + p * 256;
            int r = s >> 5, cq = s & 31;
            rW1a[p] = *(const float4*)(W1 + (size_t)tn * DD * HH + (size_t)(2 * r) * HH + cq * 4);
            rW1b[p] = *(const float4*)(W1 + (size_t)tn * DD * HH + (size_t)(2 * r + 1) * HH + cq * 4);
        }
        float rb1 = 0.f, rb2 = 0.f;
        if (tid < 128)      rb1 = b1[tn * HH + tid];
        else if (tid < 192) rb2 = b2[tn * DD + (tid - 128)];

        // GEMM1: h = relu(X @ W1 + b1)  (128x128, k=64)
        float hacc[2][8][4];
#pragma unroll
        for (int mi = 0; mi < 2; mi++)
#pragma unroll
            for (int ni = 0; ni < 8; ni++)
#pragma unroll
                for (int j = 0; j < 4; j++) hacc[mi][ni][j] = 0.f;
#pragma unroll
        for (int kk = 0; kk < 4; kk++) {
            uint32_t a[2][4], bf[8][2];
#pragma unroll
            for (int mi = 0; mi < 2; mi++) {
                int mr = wm + 16 * mi;
                a[mi][0] = Xs[(mr + g) * 36 + 8 * kk + t];
                a[mi][1] = Xs[(mr + 8 + g) * 36 + 8 * kk + t];
                a[mi][2] = Xs[(mr + g) * 36 + 8 * kk + t + 4];
                a[mi][3] = Xs[(mr + 8 + g) * 36 + 8 * kk + t + 4];
            }
#pragma unroll
            for (int ni = 0; ni < 8; ni++) {
                bf[ni][0] = W1s[(8 * kk + t) * 136 + wn1 + 8 * ni + g];
                bf[ni][1] = W1s[(8 * kk + t + 4) * 136 + wn1 + 8 * ni + g];
            }
#pragma unroll
            for (int mi = 0; mi < 2; mi++)
#pragma unroll
                for (int ni = 0; ni < 8; ni++) mma_fp16(hacc[mi][ni], a[mi], bf[ni]);
        }
        // bias + relu -> Hs (A-layout, pairs along k)
        const int wn1h = wn1 >> 1;
#pragma unroll
        for (int mi = 0; mi < 2; mi++) {
            int r1 = wm + 16 * mi + g, r2 = r1 + 8;
#pragma unroll
            for (int ni = 0; ni < 8; ni++) {
                int c = wn1 + 8 * ni + 2 * t;
                float bx = b1s[pb * 128 + c], by = b1s[pb * 128 + c + 1];
                Hs[r1 * 68 + wn1h + 4 * ni + t] =
                    h2(fmaxf(hacc[mi][ni][0] + bx, 0.f), fmaxf(hacc[mi][ni][1] + by, 0.f));
                Hs[r2 * 68 + wn1h + 4 * ni + t] =
                    h2(fmaxf(hacc[mi][ni][2] + bx, 0.f), fmaxf(hacc[mi][ni][3] + by, 0.f));
            }
        }
        __syncthreads();   // Hs visible; W1s free; next-parity biases free

        // commit prefetched W1(t+1)+biases; prefetch W2(t+1)
#pragma unroll
        for (int p = 0; p < 4; p++) {
            int s = tid + p * 256;
            int r = s >> 5, cq = s & 31;
            uint4 w;
            w.x = h2(rW1a[p].x, rW1b[p].x); w.y = h2(rW1a[p].y, rW1b[p].y);
            w.z = h2(rW1a[p].z, rW1b[p].z); w.w = h2(rW1a[p].w, rW1b[p].w);
            *(uint4*)&W1s[r * 136 + cq * 4] = w;
        }
        if (tid < 128)      b1s[(pb ^ 1) * 128 + tid]        = rb1;
        else if (tid < 192) b2s[(pb ^ 1) * 64 + (tid - 128)] = rb2;
        float4 rW2a[4], rW2b[4];
#pragma unroll
        for (int p = 0; p < 4; p++) {
            int s = tid + p * 256;
            int r = s >> 4, cq = s & 15;
            rW2a[p] = *(const float4*)(W2 + (size_t)tn * HH * DD + (size_t)(2 * r) * DD + cq * 4);
            rW2b[p] = *(const float4*)(W2 + (size_t)tn * HH * DD + (size_t)(2 * r + 1) * DD + cq * 4);
        }

        // GEMM2: acc2 = h @ W2  (128x64, k=128)
        float acc2[2][4][4];
#pragma unroll
        for (int mi = 0; mi < 2; mi++)
#pragma unroll
            for (int ni = 0; ni < 4; ni++)
#pragma unroll
                for (int j = 0; j < 4; j++) acc2[mi][ni][j] = 0.f;
#pragma unroll
        for (int kk = 0; kk < 8; kk++) {
            uint32_t a[2][4], bf[4][2];
#pragma unroll
            for (int mi = 0; mi < 2; mi++) {
                int mr = wm + 16 * mi;
                a[mi][0] = Hs[(mr + g) * 68 + 8 * kk + t];
                a[mi][1] = Hs[(mr + 8 + g) * 68 + 8 * kk + t];
                a[mi][2] = Hs[(mr + g) * 68 + 8 * kk + t + 4];
                a[mi][3] = Hs[(mr + 8 + g) * 68 + 8 * kk + t + 4];
            }
#pragma unroll
            for (int ni = 0; ni < 4; ni++) {
                bf[ni][0] = W2s[(8 * kk + t) * 72 + wn2 + 8 * ni + g];
                bf[ni][1] = W2s[(8 * kk + t + 4) * 72 + wn2 + 8 * ni + g];
            }
#pragma unroll
            for (int mi = 0; mi < 2; mi++)
#pragma unroll
                for (int ni = 0; ni < 4; ni++) mma_fp16(acc2[mi][ni], a[mi], bf[ni]);
        }
#pragma unroll
        for (int mi = 0; mi < 2; mi++) {
            int r1 = wm + 16 * mi + g, r2 = r1 + 8;
            float wA = wds[r1 * TT + et];
            float wB = wds[r2 * TT + et];
#pragma unroll
            for (int ni = 0; ni < 4; ni++) {
                int c = wn2 + 8 * ni + 2 * t;
                float bx = b2s[pb * 64 + c], by = b2s[pb * 64 + c + 1];
                Y[mi][ni][0] += wA * (acc2[mi][ni][0] + bx);
                Y[mi][ni][1] += wA * (acc2[mi][ni][1] + by);
                Y[mi][ni][2] += wB * (acc2[mi][ni][2] + bx);
                Y[mi][ni][3] += wB * (acc2[mi][ni][3] + by);
            }
        }
        __syncthreads();   // W2s free; Hs free

        // commit prefetched W2(t+1)
#pragma unroll
        for (int p = 0; p < 4; p++) {
            int s = tid + p * 256;
            int r = s >> 4, cq = s & 15;
            uint4 w;
            w.x = h2(rW2a[p].x, rW2b[p].x); w.y = h2(rW2a[p].y, rW2b[p].y);
            w.z = h2(rW2a[p].z, rW2b[p].z); w.w = h2(rW2a[p].w, rW2b[p].w);
            *(uint4*)&W2s[r * 72 + cq * 4] = w;
        }
    }

    // epilogue: pack Y -> half2 words into g_efh
    const int wn2h = wn2 >> 1;
#pragma unroll
    for (int mi = 0; mi < 2; mi++)
#pragma unroll
        for (int ni = 0; ni < 4; ni++) {
            int r1 = (int)row0 + wm + 16 * mi + g, r2 = r1 + 8;
            int cw = wn2h + 4 * ni + t;
            g_efh[(size_t)r1 * 32 + cw] = h2(Y[mi][ni][0], Y[mi][ni][1]);
            g_efh[(size_t)r2 * 32 + cw] = h2(Y[mi][ni][2], Y[mi][ni][3]);
        }
}

// ---------------------------------------------------------------------------
// K3: node_agg[b] = H[b]^T @ ef[b]  (M=512, N=64, K=1024) + concat ori
// m-tile 64 -> 512 CTAs (one full wave, ~4 CTAs/SM). 8 warps = 4m x 2n,
// warp tile 16x32. Hp [kpair][m=64] stride 72w; Bp [kpair][d] stride 72w.
// ---------------------------------------------------------------------------
#define K3_HW 72
#define K3_BW 72
#define K3_HSZ (16 * K3_HW)
#define K3_BSZ (16 * K3_BW)
#define K3_BUF (K3_HSZ + K3_BSZ)
#define K3_SMEM_BYTES (2 * K3_BUF * 4)

__global__ __launch_bounds__(256) void k3_out(const float* __restrict__ H,
                                              const float* __restrict__ ori,
                                              float* __restrict__ out) {
    extern __shared__ uint32_t sw3[];

    const int b   = blockIdx.y;
    const int n0  = blockIdx.x * 64;
    const int tid = threadIdx.x;
    const int wid = tid >> 5, lane = tid & 31;
    const int g = lane >> 2, t = lane & 3;
    const int wm = (wid >> 1) * 16, wn = (wid & 1) * 32;

    const float* Hb = H + (size_t)b * EE * NN_;
    const uint32_t* efb = g_efh + (size_t)b * EE * 32;

    float acc[4][4];
#pragma unroll
    for (int ni = 0; ni < 4; ni++)
#pragma unroll
        for (int j = 0; j < 4; j++) acc[ni][j] = 0.f;

    const int hr = tid >> 4, hcq = tid & 15;   // Hp staging: 1 slot/thread
    const int br = tid >> 4, bcq = tid & 15;   // Bp staging: 1 slot/thread

    float4 ha0, ha1;
    uint2 eb0, eb1;
    ha0 = *(const float4*)(Hb + (size_t)(2 * hr) * NN_ + n0 + hcq * 4);
    ha1 = *(const float4*)(Hb + (size_t)(2 * hr + 1) * NN_ + n0 + hcq * 4);
    eb0 = *(const uint2*)&efb[(size_t)(2 * br) * 32 + bcq * 2];
    eb1 = *(const uint2*)&efb[(size_t)(2 * br + 1) * 32 + bcq * 2];
    {
        uint32_t* Hp = sw3; uint32_t* Bp = sw3 + K3_HSZ;
        uint4 wh;
        wh.x = h2(ha0.x, ha1.x); wh.y = h2(ha0.y, ha1.y);
        wh.z = h2(ha0.z, ha1.z); wh.w = h2(ha0.w, ha1.w);
        *(uint4*)&Hp[hr * K3_HW + hcq * 4] = wh;
        uint4 wb;
        wb.x = __byte_perm(eb0.x, eb1.x, 0x5410);
        wb.y = __byte_perm(eb0.x, eb1.x, 0x7632);
        wb.z = __byte_perm(eb0.y, eb1.y, 0x5410);
        wb.w = __byte_perm(eb0.y, eb1.y, 0x7632);
        *(uint4*)&Bp[br * K3_BW + bcq * 4] = wb;
    }
    __syncthreads();

    int buf = 0;
    for (int e0 = 0; e0 < EE; e0 += 32) {
        const int en = e0 + 32;
        if (en < EE) {
            ha0 = *(const float4*)(Hb + (size_t)(en + 2 * hr) * NN_ + n0 + hcq * 4);
            ha1 = *(const float4*)(Hb + (size_t)(en + 2 * hr + 1) * NN_ + n0 + hcq * 4);
            eb0 = *(const uint2*)&efb[(size_t)(en + 2 * br) * 32 + bcq * 2];
            eb1 = *(const uint2*)&efb[(size_t)(en + 2 * br + 1) * 32 + bcq * 2];
        }
        const uint32_t* Hp = sw3 + buf * K3_BUF;
        const uint32_t* Bp = Hp + K3_HSZ;
#pragma unroll
        for (int kk = 0; kk < 2; kk++) {
            uint32_t a[4], bf[4][2];
            a[0] = Hp[(8 * kk + t) * K3_HW + wm + g];
            a[1] = Hp[(8 * kk + t) * K3_HW + wm + 8 + g];
            a[2] = Hp[(8 * kk + t + 4) * K3_HW + wm + g];
            a[3] = Hp[(8 * kk + t + 4) * K3_HW + wm + 8 + g];
#pragma unroll
            for (int ni = 0; ni < 4; ni++) {
                bf[ni][0] = Bp[(8 * kk + t) * K3_BW + wn + 8 * ni + g];
                bf[ni][1] = Bp[(8 * kk + t + 4) * K3_BW + wn + 8 * ni + g];
            }
#pragma unroll
            for (int ni = 0; ni < 4; ni++) mma_fp16(acc[ni], a, bf[ni]);
        }
        if (en < EE) {
            uint32_t* Hn = sw3 + (buf ^ 1) * K3_BUF;
            uint32_t* Bn = Hn + K3_HSZ;
            uint4 wh;
            wh.x = h2(ha0.x, ha1.x); wh.y = h2(ha0.y, ha1.y);
            wh.z = h2(ha0.z, ha1.z); wh.w = h2(ha0.w, ha1.w);
            *(uint4*)&Hn[hr * K3_HW + hcq * 4] = wh;
            uint4 wb;
            wb.x = __byte_perm(eb0.x, eb1.x, 0x5410);
            wb.y = __byte_perm(eb0.x, eb1.x, 0x7632);
            wb.z = __byte_perm(eb0.y, eb1.y, 0x5410);
            wb.w = __byte_perm(eb0.y, eb1.y, 0x7632);
            *(uint4*)&Bn[br * K3_BW + bcq * 4] = wb;
        }
        __syncthreads();
        buf ^= 1;
    }

    float*       outb = out + (size_t)b * NN_ * (2 * DD);
    const float* orib = ori + (size_t)b * NN_ * DD;
#pragma unroll
    for (int ni = 0; ni < 4; ni++) {
        int r1 = n0 + wm + g, r2 = r1 + 8;
        int c  = wn + 8 * ni + 2 * t;
        *(float2*)(outb + (size_t)r1 * (2 * DD) + c) =
            make_float2(acc[ni][0], acc[ni][1]);
        *(float2*)(outb + (size_t)r2 * (2 * DD) + c) =
            make_float2(acc[ni][2], acc[ni][3]);
    }
    // concat half: copy ori rows (64 x 64 = 1024 float4, 4/thread)
#pragma unroll
    for (int p = 0; p < 4; p++) {
        int f = tid + p * 256;
        int r = f >> 4, cq = f & 15;
        float4 v = *(const float4*)(orib + (size_t)(n0 + r) * DD + cq * 4);
        *(float4*)(outb + (size_t)(n0 + r) * (2 * DD) + DD + cq * 4) = v;
    }
}

// ---------------------------------------------------------------------------
extern "C" void kernel_launch(void* const* d_in, const int* in_sizes, int n_in,
                              void* d_out, int out_size) {
    const float* ed  = (const float*)d_in[0];
    const float* H   = (const float*)d_in[1];
    const float* ori = (const float*)d_in[2];
    const float* W1  = (const float*)d_in[3];
    const float* b1  = (const float*)d_in[4];
    const float* W2  = (const float*)d_in[5];
    const float* b2  = (const float*)d_in[6];
    float* out = (float*)d_out;

    cudaFuncSetAttribute(kf_fused, cudaFuncAttributeMaxDynamicSharedMemorySize,
                         KF_SMEM_BYTES);

    kf_fused<<<(BB * EE) / 128, 256, KF_SMEM_BYTES>>>(H, ori, ed, W1, b1, W2, b2);

    dim3 g3(NN_ / 64, BB);
    k3_out<<<g3, 256, K3_SMEM_BYTES>>>(H, ori, out);
}